// round 10
// baseline (speedup 1.0000x reference)
#include <cuda_runtime.h>
#include <cuda_fp16.h>

typedef unsigned long long u64;

#define NN     50000
#define EE     800000
#define HH     2
#define DD     32
#define HD     64
#define INDIM  64
#define ERELN  200000
#define DRELN  32

// ---------------- scratch ----------------
__device__ u64      g_hph8[NN * 16];       // half hp (edge gather + residual)
__device__ u64      g_vmidh8[NN * 16];
__device__ u64      g_vrelh8[ERELN * 16];
__device__ float2   g_es2[NN];
__device__ float2   g_sm2[NN];
__device__ float2   g_sr2[ERELN];
__device__ float    g_Mmid[INDIM * HD];
__device__ float    g_Mrel[DRELN * HD];
__device__ float    g_vb[HD];
// CSR
__device__ int      g_cnt[NN];
__device__ int      g_off[NN + 1];
__device__ int      g_cur[NN];
__device__ int4     g_csr[EE];

// ---------------- helpers ----------------
__device__ __forceinline__ u64 pack2(float lo, float hi) {
    u64 r; asm("mov.b64 %0, {%1,%2};" : "=l"(r) : "f"(lo), "f"(hi)); return r;
}
__device__ __forceinline__ void unpack2(u64 v, float& lo, float& hi) {
    asm("mov.b64 {%0,%1}, %2;" : "=f"(lo), "=f"(hi) : "l"(v));
}
__device__ __forceinline__ void ffma2(u64& d, u64 a, u64 b) {
    asm("fma.rn.f32x2 %0, %1, %2, %0;" : "+l"(d) : "l"(a), "l"(b));
}
__device__ __forceinline__ u64 addf32x2(u64 a, u64 b) {
    u64 r; asm("add.rn.f32x2 %0, %1, %2;" : "=l"(r) : "l"(a), "l"(b)); return r;
}

// ---------------- init + prep ----------------
__global__ void k_init_prep(const float* __restrict__ W_mid, const float* __restrict__ W_rel,
                            const float* __restrict__ b_mid, const float* __restrict__ b_rel,
                            const float* __restrict__ We) {
    int tid = threadIdx.x;
    if (blockIdx.x == 0) {
        __shared__ float sWe[64 * 32];
        for (int i = tid; i < 2048; i += 256) sWe[i] = We[i];
        __syncthreads();
        for (int idx = tid; idx < INDIM * HD; idx += 256) {
            int k = idx >> 6, c = idx & 63, h = c >> 5, d = c & 31;
            float acc = 0.f;
            for (int dd = 0; dd < 32; dd++)
                acc = fmaf(W_mid[k * 64 + h * 32 + dd], sWe[dd * 32 + d], acc);
            g_Mmid[idx] = acc;
        }
        for (int idx = tid; idx < DRELN * HD; idx += 256) {
            int k = idx >> 6, c = idx & 63, h = c >> 5, d = c & 31;
            float acc = 0.f;
            for (int dd = 0; dd < 32; dd++)
                acc = fmaf(W_rel[k * 64 + h * 32 + dd], sWe[(32 + dd) * 32 + d], acc);
            g_Mrel[idx] = acc;
        }
        if (tid < HD) {
            int h = tid >> 5, d = tid & 31;
            float acc = 0.f;
            for (int dd = 0; dd < 32; dd++) {
                acc = fmaf(b_mid[h * 32 + dd], sWe[dd * 32 + d], acc);
                acc = fmaf(b_rel[h * 32 + dd], sWe[(32 + dd) * 32 + d], acc);
            }
            g_vb[tid] = acc;
        }
    } else {
        int i = (blockIdx.x - 1) * 256 + tid;
        if (i < NN) g_cnt[i] = 0;
    }
}

// ---------------- CSR build ----------------
__global__ void k_hist(const int* __restrict__ dst) {
    int e = blockIdx.x * 256 + threadIdx.x;
    if (e < EE) atomicAdd(&g_cnt[dst[e]], 1);
}

__global__ void k_scan() {
    __shared__ int spart[1024];
    int t = threadIdx.x;
    const int CH = (NN + 1023) / 1024;  // 49
    int lo = t * CH, hi = min(lo + CH, NN);
    int s = 0;
    for (int i = lo; i < hi; i++) s += g_cnt[i];
    spart[t] = s;
    __syncthreads();
    for (int o = 1; o < 1024; o <<= 1) {
        int v = (t >= o) ? spart[t - o] : 0;
        __syncthreads();
        spart[t] += v;
        __syncthreads();
    }
    int run = spart[t] - s;   // exclusive prefix for this chunk
    for (int i = lo; i < hi; i++) {
        g_off[i] = run;
        g_cur[i] = run;
        run += g_cnt[i];
    }
    if (t == 1023) g_off[NN] = run;
}

__global__ void k_scatter(const int* __restrict__ src, const int* __restrict__ dst,
                          const int* __restrict__ hn,  const int* __restrict__ he) {
    int e = blockIdx.x * 256 + threadIdx.x;
    if (e >= EE) return;
    int t = dst[e];
    int pos = atomicAdd(&g_cur[t], 1);
    g_csr[pos] = make_int4(src[e], hn[e], he[e], 0);
}

// ---------------- target projection: hp(half), e_src (e_dst cancels in softmax) ----------------
__global__ void __launch_bounds__(256) k_proj_target(const float* __restrict__ x,
                              const float* __restrict__ W,
                              const float* __restrict__ b,
                              const float* __restrict__ asrc) {
    __shared__ float sx[32 * INDIM];
    __shared__ float spT[2][32][HD];
    int tid = threadIdx.x, w = tid >> 5, lane = tid & 31;
    int kh = w & 1, head = (w >> 1) & 1, slot = w >> 2;
    int n0 = blockIdx.x * 32;
    int nrows = min(32, NN - n0);
    for (int i = tid; i < nrows * 16; i += 256)
        ((float4*)sx)[i] = ((const float4*)(x + (size_t)n0 * INDIM))[i];
    int col = head * 32 + lane;
    float wreg[32];
#pragma unroll
    for (int kk = 0; kk < 32; kk++) wreg[kk] = W[(kh * 32 + kk) * HD + col];
    __syncthreads();
    for (int row = slot; row < nrows; row += 2) {
        float a0 = 0.f, a1 = 0.f, a2 = 0.f, a3 = 0.f;
        const float4* xrw = (const float4*)(sx + row * INDIM + kh * 32);
#pragma unroll
        for (int k4 = 0; k4 < 8; k4++) {
            float4 xv = xrw[k4];
            a0 = fmaf(xv.x, wreg[4 * k4 + 0], a0);
            a1 = fmaf(xv.y, wreg[4 * k4 + 1], a1);
            a2 = fmaf(xv.z, wreg[4 * k4 + 2], a2);
            a3 = fmaf(xv.w, wreg[4 * k4 + 3], a3);
        }
        spT[kh][row][col] = (a0 + a1) + (a2 + a3);
    }
    __syncthreads();
    if (kh == 0) {
        float bb = b[col];
        float as = asrc[col];
        __half* hph = (__half*)g_hph8;
        for (int row = slot; row < nrows; row += 2) {
            int n = n0 + row;
            float acc = spT[0][row][col] + spT[1][row][col] + bb;
            hph[n * HD + col] = __float2half_rn(acc);
            float vs = fmaxf(acc, 0.f) * as;
#pragma unroll
            for (int o = 16; o > 0; o >>= 1)
                vs += __shfl_down_sync(0xffffffffu, vs, o);
            if (lane == 0) ((float*)&g_es2[n])[head] = vs;
        }
    }
}

// ---------------- mid projection: paired-rows FFMA2, K split 4 ways ----------------
__global__ void __launch_bounds__(256) k_proj_mid(const float* __restrict__ x,
                           const float* __restrict__ W,
                           const float* __restrict__ b,
                           const float* __restrict__ aedge) {
    __shared__ __align__(16) u64 spx[8][INDIM];
    __shared__ __align__(16) u64 spW[4][8][64];
    __shared__ __align__(16) u64 spM[4][8][64];
    int tid = threadIdx.x, w = tid >> 5, lane = tid & 31;
    int kh = w & 3, head = w >> 2;
    int n0 = blockIdx.x * 16;
    {
        int row = tid >> 4, k4 = tid & 15;
        float4 v = ((const float4*)(x + (size_t)(n0 + row) * INDIM))[k4];
        int pair = row >> 1, sub = row & 1;
        float* bp = (float*)&spx[pair][k4 * 4];
        bp[0 + sub] = v.x; bp[2 + sub] = v.y;
        bp[4 + sub] = v.z; bp[6 + sub] = v.w;
    }
    int col = head * 32 + lane;
    u64 wdup[16], mdup[16];
#pragma unroll
    for (int kk = 0; kk < 16; kk++) {
        int k = kh * 16 + kk;
        float wv = W[k * HD + col];
        float mv = g_Mmid[k * HD + col];
        wdup[kk] = pack2(wv, wv);
        mdup[kk] = pack2(mv, mv);
    }
    __syncthreads();
#pragma unroll
    for (int p0 = 0; p0 < 4; p0++) {
        u64 dW0 = 0, dM0 = 0, dW1 = 0, dM1 = 0;
        const ulonglong2* xa = (const ulonglong2*)&spx[p0][kh * 16];
        const ulonglong2* xb = (const ulonglong2*)&spx[p0 + 4][kh * 16];
#pragma unroll
        for (int k2 = 0; k2 < 8; k2++) {
            ulonglong2 sa = xa[k2], sb = xb[k2];
            ffma2(dW0, sa.x, wdup[2 * k2 + 0]);
            ffma2(dM0, sa.x, mdup[2 * k2 + 0]);
            ffma2(dW1, sb.x, wdup[2 * k2 + 0]);
            ffma2(dM1, sb.x, mdup[2 * k2 + 0]);
            ffma2(dW0, sa.y, wdup[2 * k2 + 1]);
            ffma2(dM0, sa.y, mdup[2 * k2 + 1]);
            ffma2(dW1, sb.y, wdup[2 * k2 + 1]);
            ffma2(dM1, sb.y, mdup[2 * k2 + 1]);
        }
        spW[kh][p0][col] = dW0;  spM[kh][p0][col] = dM0;
        spW[kh][p0 + 4][col] = dW1;  spM[kh][p0 + 4][col] = dM1;
    }
    __syncthreads();
    if (kh == 0) {
        float bb = b[col];
        float av = aedge[head * 64 + lane];
        __half* vm = (__half*)g_vmidh8;
#pragma unroll
        for (int p = 0; p < 8; p++) {
            u64 uW = addf32x2(addf32x2(spW[0][p][col], spW[1][p][col]),
                              addf32x2(spW[2][p][col], spW[3][p][col]));
            u64 uM = addf32x2(addf32x2(spM[0][p][col], spM[1][p][col]),
                              addf32x2(spM[2][p][col], spM[3][p][col]));
            float aA, aB, vA, vB;
            unpack2(uW, aA, aB); unpack2(uM, vA, vB);
            aA += bb; aB += bb;
            int nA = n0 + 2 * p, nB = nA + 1;
            vm[nA * HD + col] = __float2half_rn(vA);
            vm[nB * HD + col] = __float2half_rn(vB);
            float sA = fmaxf(aA, 0.f) * av;
            float sB = fmaxf(aB, 0.f) * av;
#pragma unroll
            for (int o = 16; o > 0; o >>= 1) {
                sA += __shfl_down_sync(0xffffffffu, sA, o);
                sB += __shfl_down_sync(0xffffffffu, sB, o);
            }
            if (lane == 0) {
                ((float*)&g_sm2[nA])[head] = sA;
                ((float*)&g_sm2[nB])[head] = sB;
            }
        }
    }
}

// ---------------- rel projection: paired-rows FFMA2, K split 2 ways ----------------
__global__ void __launch_bounds__(128) k_proj_rel(const float* __restrict__ x,
                           const float* __restrict__ W,
                           const float* __restrict__ b,
                           const float* __restrict__ aedge) {
    __shared__ __align__(16) u64 spx[8][DRELN];
    __shared__ __align__(16) u64 spW[2][8][64];
    __shared__ __align__(16) u64 spM[2][8][64];
    int tid = threadIdx.x, w = tid >> 5, lane = tid & 31;
    int kh = w & 1, head = w >> 1;
    int n0 = blockIdx.x * 16;
    {
        int row = tid >> 3, k4 = tid & 7;
        float4 v = ((const float4*)(x + (size_t)(n0 + row) * DRELN))[k4];
        int pair = row >> 1, sub = row & 1;
        float* bp = (float*)&spx[pair][k4 * 4];
        bp[0 + sub] = v.x; bp[2 + sub] = v.y;
        bp[4 + sub] = v.z; bp[6 + sub] = v.w;
    }
    int col = head * 32 + lane;
    u64 wdup[16], mdup[16];
#pragma unroll
    for (int kk = 0; kk < 16; kk++) {
        int k = kh * 16 + kk;
        float wv = W[k * HD + col];
        float mv = g_Mrel[k * HD + col];
        wdup[kk] = pack2(wv, wv);
        mdup[kk] = pack2(mv, mv);
    }
    __syncthreads();
#pragma unroll
    for (int p0 = 0; p0 < 4; p0++) {
        u64 dW0 = 0, dM0 = 0, dW1 = 0, dM1 = 0;
        const ulonglong2* xa = (const ulonglong2*)&spx[p0][kh * 16];
        const ulonglong2* xb = (const ulonglong2*)&spx[p0 + 4][kh * 16];
#pragma unroll
        for (int k2 = 0; k2 < 8; k2++) {
            ulonglong2 sa = xa[k2], sb = xb[k2];
            ffma2(dW0, sa.x, wdup[2 * k2 + 0]);
            ffma2(dM0, sa.x, mdup[2 * k2 + 0]);
            ffma2(dW1, sb.x, wdup[2 * k2 + 0]);
            ffma2(dM1, sb.x, mdup[2 * k2 + 0]);
            ffma2(dW0, sa.y, wdup[2 * k2 + 1]);
            ffma2(dM0, sa.y, mdup[2 * k2 + 1]);
            ffma2(dW1, sb.y, wdup[2 * k2 + 1]);
            ffma2(dM1, sb.y, mdup[2 * k2 + 1]);
        }
        spW[kh][p0][col] = dW0;  spM[kh][p0][col] = dM0;
        spW[kh][p0 + 4][col] = dW1;  spM[kh][p0 + 4][col] = dM1;
    }
    __syncthreads();
    if (kh == 0) {
        float bb = b[col];
        float av = aedge[head * 64 + 32 + lane];
        __half* vr = (__half*)g_vrelh8;
#pragma unroll
        for (int p = 0; p < 8; p++) {
            u64 uW = addf32x2(spW[0][p][col], spW[1][p][col]);
            u64 uM = addf32x2(spM[0][p][col], spM[1][p][col]);
            float aA, aB, vA, vB;
            unpack2(uW, aA, aB); unpack2(uM, vA, vB);
            aA += bb; aB += bb;
            int nA = n0 + 2 * p, nB = nA + 1;
            vr[nA * HD + col] = __float2half_rn(vA);
            vr[nB * HD + col] = __float2half_rn(vB);
            float sA = fmaxf(aA, 0.f) * av;
            float sB = fmaxf(aB, 0.f) * av;
#pragma unroll
            for (int o = 16; o > 0; o >>= 1) {
                sA += __shfl_down_sync(0xffffffffu, sA, o);
                sB += __shfl_down_sync(0xffffffffu, sB, o);
            }
            if (lane == 0) {
                ((float*)&g_sr2[nA])[head] = sA;
                ((float*)&g_sr2[nB])[head] = sB;
            }
        }
    }
}

// ---------------- CSR aggregation + epilogue (fused final) ----------------
// one warp per dst node; 2 edges per iteration (16 lanes each)
__global__ void __launch_bounds__(256) k_agg_csr(const float* __restrict__ b_edge,
                                                 float* __restrict__ out) {
    int wid = (blockIdx.x * 256 + threadIdx.x) >> 5;
    int lane = threadIdx.x & 31;
    int g = lane >> 4, q = lane & 15;
    int n = wid;
    if (n >= NN) return;
    int beg = g_off[n], end = g_off[n + 1];
    int npair = (end - beg + 1) >> 1;
    float4 acc = make_float4(0.f, 0.f, 0.f, 0.f);
    float den0 = 0.f, den1 = 0.f;
    for (int p = 0; p < npair; p++) {
        int idx = beg + 2 * p + g;
        bool valid = idx < end;
        int4 rec = make_int4(0, 0, 0, 0);
        float ex0 = 0.f, ex1 = 0.f;
        if (q == 0 && valid) {
            rec = g_csr[idx];
            float2 es = __ldg(&g_es2[rec.x]);
            float2 sm = __ldg(&g_sm2[rec.y]);
            float2 sr = __ldg(&g_sr2[rec.z]);
            ex0 = __expf(es.x + sm.x + sr.x);
            ex1 = __expf(es.y + sm.y + sr.y);
        }
        int sl = g << 4;
        int s  = __shfl_sync(0xffffffffu, rec.x, sl);
        int mn = __shfl_sync(0xffffffffu, rec.y, sl);
        int r  = __shfl_sync(0xffffffffu, rec.z, sl);
        ex0 = __shfl_sync(0xffffffffu, ex0, sl);
        ex1 = __shfl_sync(0xffffffffu, ex1, sl);
        if (valid) {
            u64 A = __ldg(&g_hph8[(size_t)s * 16 + q]);
            u64 B = __ldg(&g_vmidh8[(size_t)mn * 16 + q]);
            u64 C = __ldg(&g_vrelh8[(size_t)r * 16 + q]);
            __half2 a01 = ((__half2*)&A)[0], a23 = ((__half2*)&A)[1];
            __half2 b01 = ((__half2*)&B)[0], b23 = ((__half2*)&B)[1];
            __half2 c01 = ((__half2*)&C)[0], c23 = ((__half2*)&C)[1];
            float2 f01 = __half22float2(__hadd2(__hadd2(a01, b01), c01));
            float2 f23 = __half22float2(__hadd2(__hadd2(a23, b23), c23));
            float ex = (q & 8) ? ex1 : ex0;
            acc.x = fmaf(ex, f01.x, acc.x);
            acc.y = fmaf(ex, f01.y, acc.y);
            acc.z = fmaf(ex, f23.x, acc.z);
            acc.w = fmaf(ex, f23.y, acc.w);
            if (q == 0) { den0 += ex0; den1 += ex1; }
        }
    }
    // combine the two 16-lane groups
    acc.x += __shfl_down_sync(0xffffffffu, acc.x, 16);
    acc.y += __shfl_down_sync(0xffffffffu, acc.y, 16);
    acc.z += __shfl_down_sync(0xffffffffu, acc.z, 16);
    acc.w += __shfl_down_sync(0xffffffffu, acc.w, 16);
    den0 += __shfl_down_sync(0xffffffffu, den0, 16);
    den1 += __shfl_down_sync(0xffffffffu, den1, 16);
    den0 = __shfl_sync(0xffffffffu, den0, 0);
    den1 = __shfl_sync(0xffffffffu, den1, 0);
    // epilogue on lanes 0..15
    float den = (q & 8) ? den1 : den0;
    float inv = (den > 0.f) ? 1.f / den : 0.f;
    float vbm = (den > 0.f) ? 1.f : 0.f;
    float4 vbq = ((const float4*)g_vb)[q];
    float4 be = ((const float4*)b_edge)[q & 7];
    u64 A = g_hph8[(size_t)n * 16 + q];
    __half2 a01 = ((__half2*)&A)[0], a23 = ((__half2*)&A)[1];
    float2 h01 = __half22float2(a01);
    float2 h23 = __half22float2(a23);
    float4 val;
    val.x = fmaxf(fmaf(acc.x, inv, vbq.x * vbm) + be.x + h01.x, 0.f);
    val.y = fmaxf(fmaf(acc.y, inv, vbq.y * vbm) + be.y + h01.y, 0.f);
    val.z = fmaxf(fmaf(acc.z, inv, vbq.z * vbm) + be.z + h23.x, 0.f);
    val.w = fmaxf(fmaf(acc.w, inv, vbq.w * vbm) + be.w + h23.y, 0.f);
    float ss = val.x * val.x + val.y * val.y + val.z * val.z + val.w * val.w;
#pragma unroll
    for (int o = 8; o > 0; o >>= 1) ss += __shfl_xor_sync(0xffffffffu, ss, o, 16);
    float rn = 1.f / fmaxf(sqrtf(ss), 1e-12f);
    if (g == 0) {
        float4 o4;
        o4.x = val.x * rn; o4.y = val.y * rn; o4.z = val.z * rn; o4.w = val.w * rn;
        ((float4*)out)[(size_t)n * 16 + q] = o4;
    }
}

extern "C" void kernel_launch(void* const* d_in, const int* in_sizes, int n_in,
                              void* d_out, int out_size) {
    const float* h         = (const float*)d_in[0];
    const float* W_t       = (const float*)d_in[1];
    const float* b_t       = (const float*)d_in[2];
    const float* nfeat_mid = (const float*)d_in[3];
    const float* W_mid     = (const float*)d_in[4];
    const float* b_mid     = (const float*)d_in[5];
    const float* efeat_rel = (const float*)d_in[6];
    const float* W_rel     = (const float*)d_in[7];
    const float* b_rel     = (const float*)d_in[8];
    const float* attn_src  = (const float*)d_in[9];
    const float* attn_edge = (const float*)d_in[11];
    const float* W_edge    = (const float*)d_in[12];
    const float* b_edge    = (const float*)d_in[13];
    const int*   src_idx   = (const int*)d_in[14];
    const int*   dst_idx   = (const int*)d_in[15];
    const int*   hn        = (const int*)d_in[16];
    const int*   he        = (const int*)d_in[17];
    float* out = (float*)d_out;

    k_init_prep<<<1 + (NN + 255) / 256, 256>>>(W_mid, W_rel, b_mid, b_rel, W_edge);
    k_hist<<<(EE + 255) / 256, 256>>>(dst_idx);
    k_proj_target<<<(NN + 31) / 32, 256>>>(h, W_t, b_t, attn_src);
    k_proj_mid<<<NN / 16, 256>>>(nfeat_mid, W_mid, b_mid, attn_edge);
    k_proj_rel<<<ERELN / 16, 128>>>(efeat_rel, W_rel, b_rel, attn_edge);
    k_scan<<<1, 1024>>>();
    k_scatter<<<(EE + 255) / 256, 256>>>(src_idx, dst_idx, hn, he);
    k_agg_csr<<<(NN * 32 + 255) / 256, 256>>>(b_edge, out);
}

// round 11
// speedup vs baseline: 1.4351x; 1.4351x over previous
#include <cuda_runtime.h>
#include <cuda_fp16.h>

typedef unsigned long long u64;

#define NN     50000
#define EE     800000
#define HH     2
#define DD     32
#define HD     64
#define INDIM  64
#define ERELN  200000
#define DRELN  32

// ---------------- scratch ----------------
__device__ u64      g_hph8[NN * 16];       // half hp (edge gather + residual)
__device__ u64      g_vmidh8[NN * 16];
__device__ u64      g_vrelh8[ERELN * 16];
__device__ float2   g_es2[NN];
__device__ float2   g_sm2[NN];
__device__ float2   g_sr2[ERELN];
__device__ float2   g_denom2[NN];
__device__ float4   g_rst4[NN * 16];
__device__ float    g_Mmid[INDIM * HD];
__device__ float    g_Mrel[DRELN * HD];
__device__ float    g_vb[HD];

// ---------------- helpers ----------------
__device__ __forceinline__ u64 pack2(float lo, float hi) {
    u64 r; asm("mov.b64 %0, {%1,%2};" : "=l"(r) : "f"(lo), "f"(hi)); return r;
}
__device__ __forceinline__ void unpack2(u64 v, float& lo, float& hi) {
    asm("mov.b64 {%0,%1}, %2;" : "=f"(lo), "=f"(hi) : "l"(v));
}
__device__ __forceinline__ void ffma2(u64& d, u64 a, u64 b) {
    asm("fma.rn.f32x2 %0, %1, %2, %0;" : "+l"(d) : "l"(a), "l"(b));
}
__device__ __forceinline__ u64 addf32x2(u64 a, u64 b) {
    u64 r; asm("add.rn.f32x2 %0, %1, %2;" : "=l"(r) : "l"(a), "l"(b)); return r;
}
__device__ __forceinline__ void red_add_v4(float* p, float4 v) {
    asm volatile("red.global.add.v4.f32 [%0], {%1,%2,%3,%4};"
                 :: "l"(p), "f"(v.x), "f"(v.y), "f"(v.z), "f"(v.w) : "memory");
}
__device__ __forceinline__ void red_add_v2(float2* p, float a, float b) {
    asm volatile("red.global.add.v2.f32 [%0], {%1,%2};"
                 :: "l"(p), "f"(a), "f"(b) : "memory");
}

// ---------------- init + prep ----------------
__global__ void k_init_prep(const float* __restrict__ W_mid, const float* __restrict__ W_rel,
                            const float* __restrict__ b_mid, const float* __restrict__ b_rel,
                            const float* __restrict__ We) {
    int tid = threadIdx.x;
    if (blockIdx.x == 0) {
        __shared__ float sWe[64 * 32];
        for (int i = tid; i < 2048; i += 256) sWe[i] = We[i];
        __syncthreads();
        for (int idx = tid; idx < INDIM * HD; idx += 256) {
            int k = idx >> 6, c = idx & 63, h = c >> 5, d = c & 31;
            float acc = 0.f;
            for (int dd = 0; dd < 32; dd++)
                acc = fmaf(W_mid[k * 64 + h * 32 + dd], sWe[dd * 32 + d], acc);
            g_Mmid[idx] = acc;
        }
        for (int idx = tid; idx < DRELN * HD; idx += 256) {
            int k = idx >> 6, c = idx & 63, h = c >> 5, d = c & 31;
            float acc = 0.f;
            for (int dd = 0; dd < 32; dd++)
                acc = fmaf(W_rel[k * 64 + h * 32 + dd], sWe[(32 + dd) * 32 + d], acc);
            g_Mrel[idx] = acc;
        }
        if (tid < HD) {
            int h = tid >> 5, d = tid & 31;
            float acc = 0.f;
            for (int dd = 0; dd < 32; dd++) {
                acc = fmaf(b_mid[h * 32 + dd], sWe[dd * 32 + d], acc);
                acc = fmaf(b_rel[h * 32 + dd], sWe[(32 + dd) * 32 + d], acc);
            }
            g_vb[tid] = acc;
        }
    } else {
        int i = (blockIdx.x - 1) * 256 + tid;
        if (i < NN * 16) g_rst4[i] = make_float4(0.f, 0.f, 0.f, 0.f);
        if (i < NN)      g_denom2[i] = make_float2(0.f, 0.f);
    }
}

// ---------------- target projection: hp(half), e_src only (e_dst cancels) ----------------
__global__ void __launch_bounds__(256) k_proj_target(const float* __restrict__ x,
                              const float* __restrict__ W,
                              const float* __restrict__ b,
                              const float* __restrict__ asrc) {
    __shared__ float sx[32 * INDIM];
    __shared__ float spT[2][32][HD];
    int tid = threadIdx.x, w = tid >> 5, lane = tid & 31;
    int kh = w & 1, head = (w >> 1) & 1, slot = w >> 2;
    int n0 = blockIdx.x * 32;
    int nrows = min(32, NN - n0);
    for (int i = tid; i < nrows * 16; i += 256)
        ((float4*)sx)[i] = ((const float4*)(x + (size_t)n0 * INDIM))[i];
    int col = head * 32 + lane;
    float wreg[32];
#pragma unroll
    for (int kk = 0; kk < 32; kk++) wreg[kk] = W[(kh * 32 + kk) * HD + col];
    __syncthreads();
    for (int row = slot; row < nrows; row += 2) {
        float a0 = 0.f, a1 = 0.f, a2 = 0.f, a3 = 0.f;
        const float4* xrw = (const float4*)(sx + row * INDIM + kh * 32);
#pragma unroll
        for (int k4 = 0; k4 < 8; k4++) {
            float4 xv = xrw[k4];
            a0 = fmaf(xv.x, wreg[4 * k4 + 0], a0);
            a1 = fmaf(xv.y, wreg[4 * k4 + 1], a1);
            a2 = fmaf(xv.z, wreg[4 * k4 + 2], a2);
            a3 = fmaf(xv.w, wreg[4 * k4 + 3], a3);
        }
        spT[kh][row][col] = (a0 + a1) + (a2 + a3);
    }
    __syncthreads();
    if (kh == 0) {
        float bb = b[col];
        float as = asrc[col];
        __half* hph = (__half*)g_hph8;
        for (int row = slot; row < nrows; row += 2) {
            int n = n0 + row;
            float acc = spT[0][row][col] + spT[1][row][col] + bb;
            hph[n * HD + col] = __float2half_rn(acc);
            float vs = fmaxf(acc, 0.f) * as;
#pragma unroll
            for (int o = 16; o > 0; o >>= 1)
                vs += __shfl_down_sync(0xffffffffu, vs, o);
            if (lane == 0) ((float*)&g_es2[n])[head] = vs;
        }
    }
}

// ---------------- mid projection: paired-rows FFMA2, K split 4 ways, STS.128 staging ----------------
// 256 thr = 8 warps: kh = w&3 (16 K each), head = w>>2; 16 rows (8 pairs)/block
__global__ void __launch_bounds__(256) k_proj_mid(const float* __restrict__ x,
                           const float* __restrict__ W,
                           const float* __restrict__ b,
                           const float* __restrict__ aedge) {
    __shared__ __align__(16) u64 spx[8][INDIM];   // (xA,xB) pairs, 4KB
    __shared__ __align__(16) u64 spW[4][8][64];   // 16KB
    __shared__ __align__(16) u64 spM[4][8][64];   // 16KB
    int tid = threadIdx.x, w = tid >> 5, lane = tid & 31;
    int kh = w & 3, head = w >> 2;
    int n0 = blockIdx.x * 16;
    if (tid < 128) {   // 8 pairs x 16 k4-chunks; 2 LDG.128 + 2 STS.128 each
        int pair = tid >> 4, k4 = tid & 15;
        const float4* rA = (const float4*)(x + (size_t)(n0 + 2 * pair) * INDIM);
        const float4* rB = (const float4*)(x + (size_t)(n0 + 2 * pair + 1) * INDIM);
        float4 vA = rA[k4], vB = rB[k4];
        ulonglong2* d = (ulonglong2*)&spx[pair][k4 * 4];
        d[0] = make_ulonglong2(pack2(vA.x, vB.x), pack2(vA.y, vB.y));
        d[1] = make_ulonglong2(pack2(vA.z, vB.z), pack2(vA.w, vB.w));
    }
    int col = head * 32 + lane;
    u64 wdup[16], mdup[16];
#pragma unroll
    for (int kk = 0; kk < 16; kk++) {
        int k = kh * 16 + kk;
        float wv = W[k * HD + col];
        float mv = g_Mmid[k * HD + col];
        wdup[kk] = pack2(wv, wv);
        mdup[kk] = pack2(mv, mv);
    }
    __syncthreads();
#pragma unroll
    for (int p0 = 0; p0 < 4; p0++) {
        u64 dW0 = 0, dM0 = 0, dW1 = 0, dM1 = 0;
        const ulonglong2* xa = (const ulonglong2*)&spx[p0][kh * 16];
        const ulonglong2* xb = (const ulonglong2*)&spx[p0 + 4][kh * 16];
#pragma unroll
        for (int k2 = 0; k2 < 8; k2++) {
            ulonglong2 sa = xa[k2], sb = xb[k2];
            ffma2(dW0, sa.x, wdup[2 * k2 + 0]);
            ffma2(dM0, sa.x, mdup[2 * k2 + 0]);
            ffma2(dW1, sb.x, wdup[2 * k2 + 0]);
            ffma2(dM1, sb.x, mdup[2 * k2 + 0]);
            ffma2(dW0, sa.y, wdup[2 * k2 + 1]);
            ffma2(dM0, sa.y, mdup[2 * k2 + 1]);
            ffma2(dW1, sb.y, wdup[2 * k2 + 1]);
            ffma2(dM1, sb.y, mdup[2 * k2 + 1]);
        }
        spW[kh][p0][col] = dW0;  spM[kh][p0][col] = dM0;
        spW[kh][p0 + 4][col] = dW1;  spM[kh][p0 + 4][col] = dM1;
    }
    __syncthreads();
    if (kh == 0) {
        float bb = b[col];
        float av = aedge[head * 64 + lane];
        __half* vm = (__half*)g_vmidh8;
#pragma unroll
        for (int p = 0; p < 8; p++) {
            u64 uW = addf32x2(addf32x2(spW[0][p][col], spW[1][p][col]),
                              addf32x2(spW[2][p][col], spW[3][p][col]));
            u64 uM = addf32x2(addf32x2(spM[0][p][col], spM[1][p][col]),
                              addf32x2(spM[2][p][col], spM[3][p][col]));
            float aA, aB, vA, vB;
            unpack2(uW, aA, aB); unpack2(uM, vA, vB);
            aA += bb; aB += bb;
            int nA = n0 + 2 * p, nB = nA + 1;
            vm[nA * HD + col] = __float2half_rn(vA);
            vm[nB * HD + col] = __float2half_rn(vB);
            float sA = fmaxf(aA, 0.f) * av;
            float sB = fmaxf(aB, 0.f) * av;
#pragma unroll
            for (int o = 16; o > 0; o >>= 1) {
                sA += __shfl_down_sync(0xffffffffu, sA, o);
                sB += __shfl_down_sync(0xffffffffu, sB, o);
            }
            if (lane == 0) {
                ((float*)&g_sm2[nA])[head] = sA;
                ((float*)&g_sm2[nB])[head] = sB;
            }
        }
    }
}

// ---------------- rel projection: paired-rows FFMA2, K split 2 ways, STS.128 staging ----------------
__global__ void __launch_bounds__(128) k_proj_rel(const float* __restrict__ x,
                           const float* __restrict__ W,
                           const float* __restrict__ b,
                           const float* __restrict__ aedge) {
    __shared__ __align__(16) u64 spx[8][DRELN];
    __shared__ __align__(16) u64 spW[2][8][64];
    __shared__ __align__(16) u64 spM[2][8][64];
    int tid = threadIdx.x, w = tid >> 5, lane = tid & 31;
    int kh = w & 1, head = w >> 1;
    int n0 = blockIdx.x * 16;
    if (tid < 64) {   // 8 pairs x 8 k4-chunks; 2 LDG.128 + 2 STS.128 each
        int pair = tid >> 3, k4 = tid & 7;
        const float4* rA = (const float4*)(x + (size_t)(n0 + 2 * pair) * DRELN);
        const float4* rB = (const float4*)(x + (size_t)(n0 + 2 * pair + 1) * DRELN);
        float4 vA = rA[k4], vB = rB[k4];
        ulonglong2* d = (ulonglong2*)&spx[pair][k4 * 4];
        d[0] = make_ulonglong2(pack2(vA.x, vB.x), pack2(vA.y, vB.y));
        d[1] = make_ulonglong2(pack2(vA.z, vB.z), pack2(vA.w, vB.w));
    }
    int col = head * 32 + lane;
    u64 wdup[16], mdup[16];
#pragma unroll
    for (int kk = 0; kk < 16; kk++) {
        int k = kh * 16 + kk;
        float wv = W[k * HD + col];
        float mv = g_Mrel[k * HD + col];
        wdup[kk] = pack2(wv, wv);
        mdup[kk] = pack2(mv, mv);
    }
    __syncthreads();
#pragma unroll
    for (int p0 = 0; p0 < 4; p0++) {
        u64 dW0 = 0, dM0 = 0, dW1 = 0, dM1 = 0;
        const ulonglong2* xa = (const ulonglong2*)&spx[p0][kh * 16];
        const ulonglong2* xb = (const ulonglong2*)&spx[p0 + 4][kh * 16];
#pragma unroll
        for (int k2 = 0; k2 < 8; k2++) {
            ulonglong2 sa = xa[k2], sb = xb[k2];
            ffma2(dW0, sa.x, wdup[2 * k2 + 0]);
            ffma2(dM0, sa.x, mdup[2 * k2 + 0]);
            ffma2(dW1, sb.x, wdup[2 * k2 + 0]);
            ffma2(dM1, sb.x, mdup[2 * k2 + 0]);
            ffma2(dW0, sa.y, wdup[2 * k2 + 1]);
            ffma2(dM0, sa.y, mdup[2 * k2 + 1]);
            ffma2(dW1, sb.y, wdup[2 * k2 + 1]);
            ffma2(dM1, sb.y, mdup[2 * k2 + 1]);
        }
        spW[kh][p0][col] = dW0;  spM[kh][p0][col] = dM0;
        spW[kh][p0 + 4][col] = dW1;  spM[kh][p0 + 4][col] = dM1;
    }
    __syncthreads();
    if (kh == 0) {
        float bb = b[col];
        float av = aedge[head * 64 + 32 + lane];
        __half* vr = (__half*)g_vrelh8;
#pragma unroll
        for (int p = 0; p < 8; p++) {
            u64 uW = addf32x2(spW[0][p][col], spW[1][p][col]);
            u64 uM = addf32x2(spM[0][p][col], spM[1][p][col]);
            float aA, aB, vA, vB;
            unpack2(uW, aA, aB); unpack2(uM, vA, vB);
            aA += bb; aB += bb;
            int nA = n0 + 2 * p, nB = nA + 1;
            vr[nA * HD + col] = __float2half_rn(vA);
            vr[nB * HD + col] = __float2half_rn(vB);
            float sA = fmaxf(aA, 0.f) * av;
            float sB = fmaxf(aB, 0.f) * av;
#pragma unroll
            for (int o = 16; o > 0; o >>= 1) {
                sA += __shfl_down_sync(0xffffffffu, sA, o);
                sB += __shfl_down_sync(0xffffffffu, sB, o);
            }
            if (lane == 0) {
                ((float*)&g_sr2[nA])[head] = sA;
                ((float*)&g_sr2[nB])[head] = sB;
            }
        }
    }
}

// ---------------- fused edge pass (fp16 gathers, no e_dst) ----------------
__global__ void k_edge_agg(const int* __restrict__ src, const int* __restrict__ dst,
                           const int* __restrict__ hn,  const int* __restrict__ he) {
    int gt = blockIdx.x * 256 + threadIdx.x;
    int e = gt >> 4;
    int q = gt & 15;
    int lane = threadIdx.x & 31;
    int s = src[e], t = dst[e], mn = hn[e], r = he[e];
    float ex0 = 0.f, ex1 = 0.f;
    if (q == 0) {
        float2 es = __ldg(&g_es2[s]);
        float2 sm = __ldg(&g_sm2[mn]);
        float2 sr = __ldg(&g_sr2[r]);
        ex0 = __expf(es.x + sm.x + sr.x);
        ex1 = __expf(es.y + sm.y + sr.y);
        red_add_v2(&g_denom2[t], ex0, ex1);
    }
    int base = lane & ~15;
    ex0 = __shfl_sync(0xffffffffu, ex0, base);
    ex1 = __shfl_sync(0xffffffffu, ex1, base);
    float ex = (q & 8) ? ex1 : ex0;
    u64 A = __ldg(&g_hph8[s * 16 + q]);
    u64 B = __ldg(&g_vmidh8[mn * 16 + q]);
    u64 C = __ldg(&g_vrelh8[r * 16 + q]);
    __half2 a01 = ((__half2*)&A)[0], a23 = ((__half2*)&A)[1];
    __half2 b01 = ((__half2*)&B)[0], b23 = ((__half2*)&B)[1];
    __half2 c01 = ((__half2*)&C)[0], c23 = ((__half2*)&C)[1];
    __half2 s01 = __hadd2(__hadd2(a01, b01), c01);
    __half2 s23 = __hadd2(__hadd2(a23, b23), c23);
    float2 f01 = __half22float2(s01);
    float2 f23 = __half22float2(s23);
    float4 v;
    v.x = ex * f01.x; v.y = ex * f01.y;
    v.z = ex * f23.x; v.w = ex * f23.y;
    red_add_v4(((float*)g_rst4) + (size_t)t * HD + q * 4, v);
}

// ---------------- final: float4/thread, 16 nodes/block, shfl-only reduction ----------------
__global__ void __launch_bounds__(256) k_final(const float* __restrict__ b_edge,
                                               float* __restrict__ out) {
    int tid = threadIdx.x;
    int nl = tid >> 4, q = tid & 15;
    int n = blockIdx.x * 16 + nl;
    int hd = q >> 3;
    float den = ((const float*)&g_denom2[n])[hd];
    float inv = (den > 0.f) ? 1.f / den : 0.f;
    float vbm = (den > 0.f) ? 1.f : 0.f;
    float4 rv = g_rst4[n * 16 + q];
    float4 vbq = ((const float4*)g_vb)[q];
    float4 be = ((const float4*)b_edge)[q & 7];
    u64 A = g_hph8[n * 16 + q];
    __half2 a01 = ((__half2*)&A)[0], a23 = ((__half2*)&A)[1];
    float2 h01 = __half22float2(a01);
    float2 h23 = __half22float2(a23);
    float4 val;
    val.x = fmaxf(fmaf(rv.x, inv, vbq.x * vbm) + be.x + h01.x, 0.f);
    val.y = fmaxf(fmaf(rv.y, inv, vbq.y * vbm) + be.y + h01.y, 0.f);
    val.z = fmaxf(fmaf(rv.z, inv, vbq.z * vbm) + be.z + h23.x, 0.f);
    val.w = fmaxf(fmaf(rv.w, inv, vbq.w * vbm) + be.w + h23.y, 0.f);
    float ss = val.x * val.x + val.y * val.y + val.z * val.z + val.w * val.w;
#pragma unroll
    for (int o = 8; o > 0; o >>= 1) ss += __shfl_xor_sync(0xffffffffu, ss, o, 16);
    float norm = fmaxf(sqrtf(ss), 1e-12f);
    float rn = 1.f / norm;
    float4 o4;
    o4.x = val.x * rn; o4.y = val.y * rn; o4.z = val.z * rn; o4.w = val.w * rn;
    ((float4*)out)[n * 16 + q] = o4;
}

extern "C" void kernel_launch(void* const* d_in, const int* in_sizes, int n_in,
                              void* d_out, int out_size) {
    const float* h         = (const float*)d_in[0];
    const float* W_t       = (const float*)d_in[1];
    const float* b_t       = (const float*)d_in[2];
    const float* nfeat_mid = (const float*)d_in[3];
    const float* W_mid     = (const float*)d_in[4];
    const float* b_mid     = (const float*)d_in[5];
    const float* efeat_rel = (const float*)d_in[6];
    const float* W_rel     = (const float*)d_in[7];
    const float* b_rel     = (const float*)d_in[8];
    const float* attn_src  = (const float*)d_in[9];
    const float* attn_edge = (const float*)d_in[11];
    const float* W_edge    = (const float*)d_in[12];
    const float* b_edge    = (const float*)d_in[13];
    const int*   src_idx   = (const int*)d_in[14];
    const int*   dst_idx   = (const int*)d_in[15];
    const int*   hn        = (const int*)d_in[16];
    const int*   he        = (const int*)d_in[17];
    float* out = (float*)d_out;

    k_init_prep<<<3126, 256>>>(W_mid, W_rel, b_mid, b_rel, W_edge);
    k_proj_target<<<(NN + 31) / 32, 256>>>(h, W_t, b_t, attn_src);
    k_proj_mid<<<NN / 16, 256>>>(nfeat_mid, W_mid, b_mid, attn_edge);
    k_proj_rel<<<ERELN / 16, 128>>>(efeat_rel, W_rel, b_rel, attn_edge);
    k_edge_agg<<<(EE * 16) / 256, 256>>>(src_idx, dst_idx, hn, he);
    k_final<<<NN / 16, 256>>>(b_edge, out);
}

// round 12
// speedup vs baseline: 1.4881x; 1.0369x over previous
#include <cuda_runtime.h>
#include <cuda_fp16.h>

typedef unsigned long long u64;

#define NN     50000
#define EE     800000
#define HH     2
#define DD     32
#define HD     64
#define INDIM  64
#define ERELN  200000
#define DRELN  32

// ---------------- scratch ----------------
__device__ u64      g_hph8[NN * 16];       // half hp (edge gather + residual)
__device__ u64      g_vmidh8[NN * 16];
__device__ u64      g_vrelh8[ERELN * 16];
__device__ float2   g_es2[NN];
__device__ float2   g_sm2[NN];
__device__ float2   g_sr2[ERELN];
__device__ float2   g_denom2[NN];
__device__ float4   g_rst4[NN * 16];
__device__ float    g_Mmid[INDIM * HD];
__device__ float    g_Mrel[DRELN * HD];
__device__ float    g_vb[HD];

// ---------------- helpers ----------------
__device__ __forceinline__ u64 pack2(float lo, float hi) {
    u64 r; asm("mov.b64 %0, {%1,%2};" : "=l"(r) : "f"(lo), "f"(hi)); return r;
}
__device__ __forceinline__ void unpack2(u64 v, float& lo, float& hi) {
    asm("mov.b64 {%0,%1}, %2;" : "=f"(lo), "=f"(hi) : "l"(v));
}
__device__ __forceinline__ void ffma2(u64& d, u64 a, u64 b) {
    asm("fma.rn.f32x2 %0, %1, %2, %0;" : "+l"(d) : "l"(a), "l"(b));
}
__device__ __forceinline__ u64 addf32x2(u64 a, u64 b) {
    u64 r; asm("add.rn.f32x2 %0, %1, %2;" : "=l"(r) : "l"(a), "l"(b)); return r;
}
__device__ __forceinline__ void red_add_v4(float* p, float4 v) {
    asm volatile("red.global.add.v4.f32 [%0], {%1,%2,%3,%4};"
                 :: "l"(p), "f"(v.x), "f"(v.y), "f"(v.z), "f"(v.w) : "memory");
}
__device__ __forceinline__ void red_add_v2(float2* p, float a, float b) {
    asm volatile("red.global.add.v2.f32 [%0], {%1,%2};"
                 :: "l"(p), "f"(a), "f"(b) : "memory");
}

// ---------------- prep: fused weight matrices (1 block) ----------------
__global__ void k_prep(const float* __restrict__ W_mid, const float* __restrict__ W_rel,
                       const float* __restrict__ b_mid, const float* __restrict__ b_rel,
                       const float* __restrict__ We) {
    int tid = threadIdx.x;
    __shared__ float sWe[64 * 32];
    for (int i = tid; i < 2048; i += 256) sWe[i] = We[i];
    __syncthreads();
    for (int idx = tid; idx < INDIM * HD; idx += 256) {
        int k = idx >> 6, c = idx & 63, h = c >> 5, d = c & 31;
        float acc = 0.f;
        for (int dd = 0; dd < 32; dd++)
            acc = fmaf(W_mid[k * 64 + h * 32 + dd], sWe[dd * 32 + d], acc);
        g_Mmid[idx] = acc;
    }
    for (int idx = tid; idx < DRELN * HD; idx += 256) {
        int k = idx >> 6, c = idx & 63, h = c >> 5, d = c & 31;
        float acc = 0.f;
        for (int dd = 0; dd < 32; dd++)
            acc = fmaf(W_rel[k * 64 + h * 32 + dd], sWe[(32 + dd) * 32 + d], acc);
        g_Mrel[idx] = acc;
    }
    if (tid < HD) {
        int h = tid >> 5, d = tid & 31;
        float acc = 0.f;
        for (int dd = 0; dd < 32; dd++) {
            acc = fmaf(b_mid[h * 32 + dd], sWe[dd * 32 + d], acc);
            acc = fmaf(b_rel[h * 32 + dd], sWe[(32 + dd) * 32 + d], acc);
        }
        g_vb[tid] = acc;
    }
}

// ---------------- zero-init accumulators ----------------
__global__ void k_init_zero() {
    int i = blockIdx.x * 256 + threadIdx.x;
    if (i < NN * 16) g_rst4[i] = make_float4(0.f, 0.f, 0.f, 0.f);
    if (i < NN)      g_denom2[i] = make_float2(0.f, 0.f);
}

// ---------------- target projection: hp(half), e_src only (e_dst cancels) ----------------
__global__ void __launch_bounds__(256) k_proj_target(const float* __restrict__ x,
                              const float* __restrict__ W,
                              const float* __restrict__ b,
                              const float* __restrict__ asrc) {
    __shared__ float sx[32 * INDIM];
    __shared__ float spT[2][32][HD];
    int tid = threadIdx.x, w = tid >> 5, lane = tid & 31;
    int kh = w & 1, head = (w >> 1) & 1, slot = w >> 2;
    int n0 = blockIdx.x * 32;
    int nrows = min(32, NN - n0);
    for (int i = tid; i < nrows * 16; i += 256)
        ((float4*)sx)[i] = ((const float4*)(x + (size_t)n0 * INDIM))[i];
    int col = head * 32 + lane;
    float wreg[32];
#pragma unroll
    for (int kk = 0; kk < 32; kk++) wreg[kk] = W[(kh * 32 + kk) * HD + col];
    __syncthreads();
    for (int row = slot; row < nrows; row += 2) {
        float a0 = 0.f, a1 = 0.f, a2 = 0.f, a3 = 0.f;
        const float4* xrw = (const float4*)(sx + row * INDIM + kh * 32);
#pragma unroll
        for (int k4 = 0; k4 < 8; k4++) {
            float4 xv = xrw[k4];
            a0 = fmaf(xv.x, wreg[4 * k4 + 0], a0);
            a1 = fmaf(xv.y, wreg[4 * k4 + 1], a1);
            a2 = fmaf(xv.z, wreg[4 * k4 + 2], a2);
            a3 = fmaf(xv.w, wreg[4 * k4 + 3], a3);
        }
        spT[kh][row][col] = (a0 + a1) + (a2 + a3);
    }
    __syncthreads();
    if (kh == 0) {
        float bb = b[col];
        float as = asrc[col];
        __half* hph = (__half*)g_hph8;
        for (int row = slot; row < nrows; row += 2) {
            int n = n0 + row;
            float acc = spT[0][row][col] + spT[1][row][col] + bb;
            hph[n * HD + col] = __float2half_rn(acc);
            float vs = fmaxf(acc, 0.f) * as;
#pragma unroll
            for (int o = 16; o > 0; o >>= 1)
                vs += __shfl_down_sync(0xffffffffu, vs, o);
            if (lane == 0) ((float*)&g_es2[n])[head] = vs;
        }
    }
}

// ---------------- mid projection: paired-rows FFMA2, K split 4 ways ----------------
__global__ void __launch_bounds__(256) k_proj_mid(const float* __restrict__ x,
                           const float* __restrict__ W,
                           const float* __restrict__ b,
                           const float* __restrict__ aedge) {
    __shared__ __align__(16) u64 spx[8][INDIM];   // (xA,xB) pairs, 4KB
    __shared__ __align__(16) u64 spW[4][8][64];   // 16KB
    __shared__ __align__(16) u64 spM[4][8][64];   // 16KB
    int tid = threadIdx.x, w = tid >> 5, lane = tid & 31;
    int kh = w & 3, head = w >> 2;
    int n0 = blockIdx.x * 16;
    if (tid < 128) {
        int pair = tid >> 4, k4 = tid & 15;
        const float4* rA = (const float4*)(x + (size_t)(n0 + 2 * pair) * INDIM);
        const float4* rB = (const float4*)(x + (size_t)(n0 + 2 * pair + 1) * INDIM);
        float4 vA = rA[k4], vB = rB[k4];
        ulonglong2* d = (ulonglong2*)&spx[pair][k4 * 4];
        d[0] = make_ulonglong2(pack2(vA.x, vB.x), pack2(vA.y, vB.y));
        d[1] = make_ulonglong2(pack2(vA.z, vB.z), pack2(vA.w, vB.w));
    }
    int col = head * 32 + lane;
    u64 wdup[16], mdup[16];
#pragma unroll
    for (int kk = 0; kk < 16; kk++) {
        int k = kh * 16 + kk;
        float wv = W[k * HD + col];
        float mv = g_Mmid[k * HD + col];
        wdup[kk] = pack2(wv, wv);
        mdup[kk] = pack2(mv, mv);
    }
    __syncthreads();
#pragma unroll
    for (int p0 = 0; p0 < 4; p0++) {
        u64 dW0 = 0, dM0 = 0, dW1 = 0, dM1 = 0;
        const ulonglong2* xa = (const ulonglong2*)&spx[p0][kh * 16];
        const ulonglong2* xb = (const ulonglong2*)&spx[p0 + 4][kh * 16];
#pragma unroll
        for (int k2 = 0; k2 < 8; k2++) {
            ulonglong2 sa = xa[k2], sb = xb[k2];
            ffma2(dW0, sa.x, wdup[2 * k2 + 0]);
            ffma2(dM0, sa.x, mdup[2 * k2 + 0]);
            ffma2(dW1, sb.x, wdup[2 * k2 + 0]);
            ffma2(dM1, sb.x, mdup[2 * k2 + 0]);
            ffma2(dW0, sa.y, wdup[2 * k2 + 1]);
            ffma2(dM0, sa.y, mdup[2 * k2 + 1]);
            ffma2(dW1, sb.y, wdup[2 * k2 + 1]);
            ffma2(dM1, sb.y, mdup[2 * k2 + 1]);
        }
        spW[kh][p0][col] = dW0;  spM[kh][p0][col] = dM0;
        spW[kh][p0 + 4][col] = dW1;  spM[kh][p0 + 4][col] = dM1;
    }
    __syncthreads();
    if (kh == 0) {
        float bb = b[col];
        float av = aedge[head * 64 + lane];
        __half* vm = (__half*)g_vmidh8;
#pragma unroll
        for (int p = 0; p < 8; p++) {
            u64 uW = addf32x2(addf32x2(spW[0][p][col], spW[1][p][col]),
                              addf32x2(spW[2][p][col], spW[3][p][col]));
            u64 uM = addf32x2(addf32x2(spM[0][p][col], spM[1][p][col]),
                              addf32x2(spM[2][p][col], spM[3][p][col]));
            float aA, aB, vA, vB;
            unpack2(uW, aA, aB); unpack2(uM, vA, vB);
            aA += bb; aB += bb;
            int nA = n0 + 2 * p, nB = nA + 1;
            vm[nA * HD + col] = __float2half_rn(vA);
            vm[nB * HD + col] = __float2half_rn(vB);
            float sA = fmaxf(aA, 0.f) * av;
            float sB = fmaxf(aB, 0.f) * av;
#pragma unroll
            for (int o = 16; o > 0; o >>= 1) {
                sA += __shfl_down_sync(0xffffffffu, sA, o);
                sB += __shfl_down_sync(0xffffffffu, sB, o);
            }
            if (lane == 0) {
                ((float*)&g_sm2[nA])[head] = sA;
                ((float*)&g_sm2[nB])[head] = sB;
            }
        }
    }
}

// ---------------- rel projection: paired-rows FFMA2, K split 2 ways ----------------
__global__ void __launch_bounds__(128) k_proj_rel(const float* __restrict__ x,
                           const float* __restrict__ W,
                           const float* __restrict__ b,
                           const float* __restrict__ aedge) {
    __shared__ __align__(16) u64 spx[8][DRELN];
    __shared__ __align__(16) u64 spW[2][8][64];
    __shared__ __align__(16) u64 spM[2][8][64];
    int tid = threadIdx.x, w = tid >> 5, lane = tid & 31;
    int kh = w & 1, head = w >> 1;
    int n0 = blockIdx.x * 16;
    if (tid < 64) {
        int pair = tid >> 3, k4 = tid & 7;
        const float4* rA = (const float4*)(x + (size_t)(n0 + 2 * pair) * DRELN);
        const float4* rB = (const float4*)(x + (size_t)(n0 + 2 * pair + 1) * DRELN);
        float4 vA = rA[k4], vB = rB[k4];
        ulonglong2* d = (ulonglong2*)&spx[pair][k4 * 4];
        d[0] = make_ulonglong2(pack2(vA.x, vB.x), pack2(vA.y, vB.y));
        d[1] = make_ulonglong2(pack2(vA.z, vB.z), pack2(vA.w, vB.w));
    }
    int col = head * 32 + lane;
    u64 wdup[16], mdup[16];
#pragma unroll
    for (int kk = 0; kk < 16; kk++) {
        int k = kh * 16 + kk;
        float wv = W[k * HD + col];
        float mv = g_Mrel[k * HD + col];
        wdup[kk] = pack2(wv, wv);
        mdup[kk] = pack2(mv, mv);
    }
    __syncthreads();
#pragma unroll
    for (int p0 = 0; p0 < 4; p0++) {
        u64 dW0 = 0, dM0 = 0, dW1 = 0, dM1 = 0;
        const ulonglong2* xa = (const ulonglong2*)&spx[p0][kh * 16];
        const ulonglong2* xb = (const ulonglong2*)&spx[p0 + 4][kh * 16];
#pragma unroll
        for (int k2 = 0; k2 < 8; k2++) {
            ulonglong2 sa = xa[k2], sb = xb[k2];
            ffma2(dW0, sa.x, wdup[2 * k2 + 0]);
            ffma2(dM0, sa.x, mdup[2 * k2 + 0]);
            ffma2(dW1, sb.x, wdup[2 * k2 + 0]);
            ffma2(dM1, sb.x, mdup[2 * k2 + 0]);
            ffma2(dW0, sa.y, wdup[2 * k2 + 1]);
            ffma2(dM0, sa.y, mdup[2 * k2 + 1]);
            ffma2(dW1, sb.y, wdup[2 * k2 + 1]);
            ffma2(dM1, sb.y, mdup[2 * k2 + 1]);
        }
        spW[kh][p0][col] = dW0;  spM[kh][p0][col] = dM0;
        spW[kh][p0 + 4][col] = dW1;  spM[kh][p0 + 4][col] = dM1;
    }
    __syncthreads();
    if (kh == 0) {
        float bb = b[col];
        float av = aedge[head * 64 + 32 + lane];
        __half* vr = (__half*)g_vrelh8;
#pragma unroll
        for (int p = 0; p < 8; p++) {
            u64 uW = addf32x2(spW[0][p][col], spW[1][p][col]);
            u64 uM = addf32x2(spM[0][p][col], spM[1][p][col]);
            float aA, aB, vA, vB;
            unpack2(uW, aA, aB); unpack2(uM, vA, vB);
            aA += bb; aB += bb;
            int nA = n0 + 2 * p, nB = nA + 1;
            vr[nA * HD + col] = __float2half_rn(vA);
            vr[nB * HD + col] = __float2half_rn(vB);
            float sA = fmaxf(aA, 0.f) * av;
            float sB = fmaxf(aB, 0.f) * av;
#pragma unroll
            for (int o = 16; o > 0; o >>= 1) {
                sA += __shfl_down_sync(0xffffffffu, sA, o);
                sB += __shfl_down_sync(0xffffffffu, sB, o);
            }
            if (lane == 0) {
                ((float*)&g_sr2[nA])[head] = sA;
                ((float*)&g_sr2[nB])[head] = sB;
            }
        }
    }
}

// ---------------- fused edge pass (fp16 gathers, no e_dst) ----------------
__global__ void k_edge_agg(const int* __restrict__ src, const int* __restrict__ dst,
                           const int* __restrict__ hn,  const int* __restrict__ he) {
    int gt = blockIdx.x * 256 + threadIdx.x;
    int e = gt >> 4;
    int q = gt & 15;
    int lane = threadIdx.x & 31;
    int s = src[e], t = dst[e], mn = hn[e], r = he[e];
    float ex0 = 0.f, ex1 = 0.f;
    if (q == 0) {
        float2 es = __ldg(&g_es2[s]);
        float2 sm = __ldg(&g_sm2[mn]);
        float2 sr = __ldg(&g_sr2[r]);
        ex0 = __expf(es.x + sm.x + sr.x);
        ex1 = __expf(es.y + sm.y + sr.y);
        red_add_v2(&g_denom2[t], ex0, ex1);
    }
    int base = lane & ~15;
    ex0 = __shfl_sync(0xffffffffu, ex0, base);
    ex1 = __shfl_sync(0xffffffffu, ex1, base);
    float ex = (q & 8) ? ex1 : ex0;
    u64 A = __ldg(&g_hph8[s * 16 + q]);
    u64 B = __ldg(&g_vmidh8[mn * 16 + q]);
    u64 C = __ldg(&g_vrelh8[r * 16 + q]);
    __half2 a01 = ((__half2*)&A)[0], a23 = ((__half2*)&A)[1];
    __half2 b01 = ((__half2*)&B)[0], b23 = ((__half2*)&B)[1];
    __half2 c01 = ((__half2*)&C)[0], c23 = ((__half2*)&C)[1];
    __half2 s01 = __hadd2(__hadd2(a01, b01), c01);
    __half2 s23 = __hadd2(__hadd2(a23, b23), c23);
    float2 f01 = __half22float2(s01);
    float2 f23 = __half22float2(s23);
    float4 v;
    v.x = ex * f01.x; v.y = ex * f01.y;
    v.z = ex * f23.x; v.w = ex * f23.y;
    red_add_v4(((float*)g_rst4) + (size_t)t * HD + q * 4, v);
}

// ---------------- final: float4/thread, 16 nodes/block ----------------
__global__ void __launch_bounds__(256) k_final(const float* __restrict__ b_edge,
                                               float* __restrict__ out) {
    int tid = threadIdx.x;
    int nl = tid >> 4, q = tid & 15;
    int n = blockIdx.x * 16 + nl;
    int hd = q >> 3;
    float den = ((const float*)&g_denom2[n])[hd];
    float inv = (den > 0.f) ? 1.f / den : 0.f;
    float vbm = (den > 0.f) ? 1.f : 0.f;
    float4 rv = g_rst4[n * 16 + q];
    float4 vbq = ((const float4*)g_vb)[q];
    float4 be = ((const float4*)b_edge)[q & 7];
    u64 A = g_hph8[n * 16 + q];
    __half2 a01 = ((__half2*)&A)[0], a23 = ((__half2*)&A)[1];
    float2 h01 = __half22float2(a01);
    float2 h23 = __half22float2(a23);
    float4 val;
    val.x = fmaxf(fmaf(rv.x, inv, vbq.x * vbm) + be.x + h01.x, 0.f);
    val.y = fmaxf(fmaf(rv.y, inv, vbq.y * vbm) + be.y + h01.y, 0.f);
    val.z = fmaxf(fmaf(rv.z, inv, vbq.z * vbm) + be.z + h23.x, 0.f);
    val.w = fmaxf(fmaf(rv.w, inv, vbq.w * vbm) + be.w + h23.y, 0.f);
    float ss = val.x * val.x + val.y * val.y + val.z * val.z + val.w * val.w;
#pragma unroll
    for (int o = 8; o > 0; o >>= 1) ss += __shfl_xor_sync(0xffffffffu, ss, o, 16);
    float norm = fmaxf(sqrtf(ss), 1e-12f);
    float rn = 1.f / norm;
    float4 o4;
    o4.x = val.x * rn; o4.y = val.y * rn; o4.z = val.z * rn; o4.w = val.w * rn;
    ((float4*)out)[n * 16 + q] = o4;
}

extern "C" void kernel_launch(void* const* d_in, const int* in_sizes, int n_in,
                              void* d_out, int out_size) {
    const float* h         = (const float*)d_in[0];
    const float* W_t       = (const float*)d_in[1];
    const float* b_t       = (const float*)d_in[2];
    const float* nfeat_mid = (const float*)d_in[3];
    const float* W_mid     = (const float*)d_in[4];
    const float* b_mid     = (const float*)d_in[5];
    const float* efeat_rel = (const float*)d_in[6];
    const float* W_rel     = (const float*)d_in[7];
    const float* b_rel     = (const float*)d_in[8];
    const float* attn_src  = (const float*)d_in[9];
    const float* attn_edge = (const float*)d_in[11];
    const float* W_edge    = (const float*)d_in[12];
    const float* b_edge    = (const float*)d_in[13];
    const int*   src_idx   = (const int*)d_in[14];
    const int*   dst_idx   = (const int*)d_in[15];
    const int*   hn        = (const int*)d_in[16];
    const int*   he        = (const int*)d_in[17];
    float* out = (float*)d_out;

    // lazily created once (on the uncaptured correctness call); reused
    // identically on every subsequent call so the captured graph is fixed.
    static cudaStream_t sB = 0, sC = 0, sD = 0;
    static cudaEvent_t evFork = 0, evB = 0, evC = 0, evD = 0;
    if (sB == 0) {
        cudaStreamCreateWithFlags(&sB, cudaStreamNonBlocking);
        cudaStreamCreateWithFlags(&sC, cudaStreamNonBlocking);
        cudaStreamCreateWithFlags(&sD, cudaStreamNonBlocking);
        cudaEventCreateWithFlags(&evFork, cudaEventDisableTiming);
        cudaEventCreateWithFlags(&evB, cudaEventDisableTiming);
        cudaEventCreateWithFlags(&evC, cudaEventDisableTiming);
        cudaEventCreateWithFlags(&evD, cudaEventDisableTiming);
    }

    // main stream: prep (Mmid/Mrel/vb) then fork
    k_prep<<<1, 256>>>(W_mid, W_rel, b_mid, b_rel, W_edge);
    cudaEventRecord(evFork, 0);

    // branch B: target projection (independent of prep, but forked after it)
    cudaStreamWaitEvent(sB, evFork, 0);
    k_proj_target<<<(NN + 31) / 32, 256, 0, sB>>>(h, W_t, b_t, attn_src);
    cudaEventRecord(evB, sB);

    // branch C: mid projection (needs g_Mmid from prep)
    cudaStreamWaitEvent(sC, evFork, 0);
    k_proj_mid<<<NN / 16, 256, 0, sC>>>(nfeat_mid, W_mid, b_mid, attn_edge);
    cudaEventRecord(evC, sC);

    // branch D: rel projection (needs g_Mrel from prep)
    cudaStreamWaitEvent(sD, evFork, 0);
    k_proj_rel<<<ERELN / 16, 128, 0, sD>>>(efeat_rel, W_rel, b_rel, attn_edge);
    cudaEventRecord(evD, sD);

    // main stream meanwhile: zero the accumulators (overlaps the projections)
    k_init_zero<<<(NN * 16 + 255) / 256, 256>>>();

    // join: edge aggregation needs everything
    cudaStreamWaitEvent(0, evB, 0);
    cudaStreamWaitEvent(0, evC, 0);
    cudaStreamWaitEvent(0, evD, 0);
    k_edge_agg<<<(EE * 16) / 256, 256>>>(src_idx, dst_idx, hn, he);
    k_final<<<NN / 16, 256>>>(b_edge, out);
}

// round 16
// speedup vs baseline: 1.6650x; 1.1189x over previous
#include <cuda_runtime.h>
#include <cuda_fp16.h>
#include <mma.h>

using namespace nvcuda;

typedef unsigned long long u64;

#define NN     50000
#define EE     800000
#define HH     2
#define DD     32
#define HD     64
#define INDIM  64
#define ERELN  200000
#define DRELN  32

// ---------------- scratch ----------------
__device__ u64      g_hph8[NN * 16];       // half hp (edge gather + residual)
__device__ u64      g_vmidh8[NN * 16];
__device__ u64      g_vrelh8[ERELN * 16];
__device__ float2   g_es2[NN];
__device__ float2   g_sm2[NN];
__device__ float2   g_sr2[ERELN];
__device__ float2   g_denom2[NN];
__device__ float4   g_rst4[NN * 16];
__device__ __half   g_Bmid_h[INDIM * 128];   // [k][n]: W_mid | W_mid@We_top
__device__ __half   g_Brel_h[DRELN * 128];   // [k][n]: W_rel | W_rel@We_bot
__device__ float    g_vb[HD];

// ---------------- helpers (identical to R12) ----------------
__device__ __forceinline__ void red_add_v4(float* p, float4 v) {
    asm volatile("red.global.add.v4.f32 [%0], {%1,%2,%3,%4};"
                 :: "l"(p), "f"(v.x), "f"(v.y), "f"(v.z), "f"(v.w) : "memory");
}
__device__ __forceinline__ void red_add_v2(float2* p, float a, float b) {
    asm volatile("red.global.add.v2.f32 [%0], {%1,%2};"
                 :: "l"(p), "f"(a), "f"(b) : "memory");
}

// ---------------- prep: fp16 fused B matrices + vb (1 block) ----------------
__global__ void k_prep(const float* __restrict__ W_mid, const float* __restrict__ W_rel,
                       const float* __restrict__ b_mid, const float* __restrict__ b_rel,
                       const float* __restrict__ We) {
    int tid = threadIdx.x;
    __shared__ float sWe[64 * 32];
    for (int i = tid; i < 2048; i += 256) sWe[i] = We[i];
    __syncthreads();
    for (int idx = tid; idx < INDIM * 128; idx += 256) {
        int k = idx >> 7;
        int n = idx & 127;
        float v;
        if (n < 64) {
            v = W_mid[k * 64 + n];
        } else {
            int c = n - 64;
            int hh = c >> 5;
            int d = c & 31;
            float acc = 0.f;
            for (int dd = 0; dd < 32; dd++)
                acc = fmaf(W_mid[k * 64 + hh * 32 + dd], sWe[dd * 32 + d], acc);
            v = acc;
        }
        g_Bmid_h[idx] = __float2half(v);
    }
    for (int idx = tid; idx < DRELN * 128; idx += 256) {
        int k = idx >> 7;
        int n = idx & 127;
        float v;
        if (n < 64) {
            v = W_rel[k * 64 + n];
        } else {
            int c = n - 64;
            int hh = c >> 5;
            int d = c & 31;
            float acc = 0.f;
            for (int dd = 0; dd < 32; dd++)
                acc = fmaf(W_rel[k * 64 + hh * 32 + dd], sWe[(32 + dd) * 32 + d], acc);
            v = acc;
        }
        g_Brel_h[idx] = __float2half(v);
    }
    if (tid < HD) {
        int hh = tid >> 5;
        int d = tid & 31;
        float acc = 0.f;
        for (int dd = 0; dd < 32; dd++) {
            acc = fmaf(b_mid[hh * 32 + dd], sWe[dd * 32 + d], acc);
            acc = fmaf(b_rel[hh * 32 + dd], sWe[(32 + dd) * 32 + d], acc);
        }
        g_vb[tid] = acc;
    }
}

// ---------------- zero-init accumulators ----------------
__global__ void k_init_zero() {
    int i = blockIdx.x * 256 + threadIdx.x;
    if (i < NN * 16) g_rst4[i] = make_float4(0.f, 0.f, 0.f, 0.f);
    if (i < NN)      g_denom2[i] = make_float2(0.f, 0.f);
}

// ---------------- mid projection via wmma: [16 x 64] @ [64 x 128] ----------------
// 128 thr = 4 warps; warp w owns output cols [w*32, w*32+32) (two 16x16 n-tiles).
__global__ void __launch_bounds__(128) k_mma_mid(const float* __restrict__ x,
                                                 const float* __restrict__ bias,
                                                 const float* __restrict__ aedge) {
    __shared__ __half sB[64][136];
    __shared__ __half sA[16][72];
    __shared__ float  sC[16][136];
    __shared__ float  sBias[64];
    __shared__ float  sAttn[64];
    int tid = threadIdx.x;
    int w = tid >> 5;

    // stage B (64x128 halves = 1024 uint4)
    for (int i = tid; i < 1024; i += 128) {
        int r = i >> 4;
        int c = i & 15;
        ((uint4*)&sB[r][0])[c] = ((const uint4*)g_Bmid_h)[i];
    }
    if (tid < 64) {
        sBias[tid] = bias[tid];
        sAttn[tid] = aedge[(tid >> 5) * 64 + (tid & 31)];
    }
    int row0 = blockIdx.x * 16;
    // stage A: 16 rows x 64 f32 -> half (256 float4)
    for (int i = tid; i < 256; i += 128) {
        int r = i >> 4;
        int c4 = i & 15;
        float4 v = ((const float4*)(x + (size_t)(row0 + r) * 64))[c4];
        __half2* d2 = (__half2*)&sA[r][c4 * 4];
        d2[0] = __floats2half2_rn(v.x, v.y);
        d2[1] = __floats2half2_rn(v.z, v.w);
    }
    __syncthreads();

    wmma::fragment<wmma::matrix_a, 16, 16, 16, __half, wmma::row_major> fa;
    wmma::fragment<wmma::matrix_b, 16, 16, 16, __half, wmma::row_major> fb;
    wmma::fragment<wmma::accumulator, 16, 16, 16, float> fc0;
    wmma::fragment<wmma::accumulator, 16, 16, 16, float> fc1;
    wmma::fill_fragment(fc0, 0.f);
    wmma::fill_fragment(fc1, 0.f);
    for (int ks = 0; ks < 4; ks++) {
        wmma::load_matrix_sync(fa, &sA[0][ks * 16], 72);
        wmma::load_matrix_sync(fb, &sB[ks * 16][w * 32], 136);
        wmma::mma_sync(fc0, fa, fb, fc0);
        wmma::load_matrix_sync(fb, &sB[ks * 16][w * 32 + 16], 136);
        wmma::mma_sync(fc1, fa, fb, fc1);
    }
    wmma::store_matrix_sync(&sC[0][w * 32], fc0, 136, wmma::mem_row_major);
    wmma::store_matrix_sync(&sC[0][w * 32 + 16], fc1, 136, wmma::mem_row_major);
    __syncthreads();

    // epilogue 1: logits from cols 0..63 (8 threads per row, 8 cols each)
    {
        int r = tid >> 3;
        int g = tid & 7;
        float p = 0.f;
#pragma unroll
        for (int j = 0; j < 8; j++) {
            int col = g * 8 + j;
            p += fmaxf(sC[r][col] + sBias[col], 0.f) * sAttn[col];
        }
        p += __shfl_xor_sync(0xffffffffu, p, 1);
        p += __shfl_xor_sync(0xffffffffu, p, 2);
        float other = __shfl_xor_sync(0xffffffffu, p, 4);
        if (g == 0) g_sm2[row0 + r] = make_float2(p, other);
    }
    // epilogue 2: fp16 table from cols 64..127 (256 u64)
    for (int i = tid; i < 256; i += 128) {
        int r = i >> 4;
        int c = i & 15;
        const float* cp = &sC[r][64 + c * 4];
        __half2 lo = __floats2half2_rn(cp[0], cp[1]);
        __half2 hi = __floats2half2_rn(cp[2], cp[3]);
        unsigned ulo = *(unsigned*)&lo;
        unsigned uhi = *(unsigned*)&hi;
        g_vmidh8[(size_t)(row0 + r) * 16 + c] = ((u64)uhi << 32) | (u64)ulo;
    }
}

// ---------------- rel projection via wmma: [16 x 32] @ [32 x 128] ----------------
__global__ void __launch_bounds__(128) k_mma_rel(const float* __restrict__ x,
                                                 const float* __restrict__ bias,
                                                 const float* __restrict__ aedge) {
    __shared__ __half sB[32][136];
    __shared__ __half sA[16][40];
    __shared__ float  sC[16][136];
    __shared__ float  sBias[64];
    __shared__ float  sAttn[64];
    int tid = threadIdx.x;
    int w = tid >> 5;

    // stage B (32x128 halves = 512 uint4)
    for (int i = tid; i < 512; i += 128) {
        int r = i >> 4;
        int c = i & 15;
        ((uint4*)&sB[r][0])[c] = ((const uint4*)g_Brel_h)[i];
    }
    if (tid < 64) {
        sBias[tid] = bias[tid];
        sAttn[tid] = aedge[(tid >> 5) * 64 + 32 + (tid & 31)];
    }
    int row0 = blockIdx.x * 16;
    // stage A: 16 rows x 32 f32 -> half (128 float4)
    {
        int i = tid;
        int r = i >> 3;
        int c4 = i & 7;
        float4 v = ((const float4*)(x + (size_t)(row0 + r) * 32))[c4];
        __half2* d2 = (__half2*)&sA[r][c4 * 4];
        d2[0] = __floats2half2_rn(v.x, v.y);
        d2[1] = __floats2half2_rn(v.z, v.w);
    }
    __syncthreads();

    wmma::fragment<wmma::matrix_a, 16, 16, 16, __half, wmma::row_major> fa;
    wmma::fragment<wmma::matrix_b, 16, 16, 16, __half, wmma::row_major> fb;
    wmma::fragment<wmma::accumulator, 16, 16, 16, float> fc0;
    wmma::fragment<wmma::accumulator, 16, 16, 16, float> fc1;
    wmma::fill_fragment(fc0, 0.f);
    wmma::fill_fragment(fc1, 0.f);
    for (int ks = 0; ks < 2; ks++) {
        wmma::load_matrix_sync(fa, &sA[0][ks * 16], 40);
        wmma::load_matrix_sync(fb, &sB[ks * 16][w * 32], 136);
        wmma::mma_sync(fc0, fa, fb, fc0);
        wmma::load_matrix_sync(fb, &sB[ks * 16][w * 32 + 16], 136);
        wmma::mma_sync(fc1, fa, fb, fc1);
    }
    wmma::store_matrix_sync(&sC[0][w * 32], fc0, 136, wmma::mem_row_major);
    wmma::store_matrix_sync(&sC[0][w * 32 + 16], fc1, 136, wmma::mem_row_major);
    __syncthreads();

    {
        int r = tid >> 3;
        int g = tid & 7;
        float p = 0.f;
#pragma unroll
        for (int j = 0; j < 8; j++) {
            int col = g * 8 + j;
            p += fmaxf(sC[r][col] + sBias[col], 0.f) * sAttn[col];
        }
        p += __shfl_xor_sync(0xffffffffu, p, 1);
        p += __shfl_xor_sync(0xffffffffu, p, 2);
        float other = __shfl_xor_sync(0xffffffffu, p, 4);
        if (g == 0) g_sr2[row0 + r] = make_float2(p, other);
    }
    for (int i = tid; i < 256; i += 128) {
        int r = i >> 4;
        int c = i & 15;
        const float* cp = &sC[r][64 + c * 4];
        __half2 lo = __floats2half2_rn(cp[0], cp[1]);
        __half2 hi = __floats2half2_rn(cp[2], cp[3]);
        unsigned ulo = *(unsigned*)&lo;
        unsigned uhi = *(unsigned*)&hi;
        g_vrelh8[(size_t)(row0 + r) * 16 + c] = ((u64)uhi << 32) | (u64)ulo;
    }
}

// ---------------- target projection: hp(half), e_src only (e_dst cancels) ----------------
__global__ void __launch_bounds__(256) k_proj_target(const float* __restrict__ x,
                              const float* __restrict__ W,
                              const float* __restrict__ b,
                              const float* __restrict__ asrc) {
    __shared__ float sx[32 * INDIM];
    __shared__ float spT[2][32][HD];
    int tid = threadIdx.x, w = tid >> 5, lane = tid & 31;
    int kh = w & 1, head = (w >> 1) & 1, slot = w >> 2;
    int n0 = blockIdx.x * 32;
    int nrows = min(32, NN - n0);
    for (int i = tid; i < nrows * 16; i += 256)
        ((float4*)sx)[i] = ((const float4*)(x + (size_t)n0 * INDIM))[i];
    int col = head * 32 + lane;
    float wreg[32];
#pragma unroll
    for (int kk = 0; kk < 32; kk++) wreg[kk] = W[(kh * 32 + kk) * HD + col];
    __syncthreads();
    for (int row = slot; row < nrows; row += 2) {
        float a0 = 0.f, a1 = 0.f, a2 = 0.f, a3 = 0.f;
        const float4* xrw = (const float4*)(sx + row * INDIM + kh * 32);
#pragma unroll
        for (int k4 = 0; k4 < 8; k4++) {
            float4 xv = xrw[k4];
            a0 = fmaf(xv.x, wreg[4 * k4 + 0], a0);
            a1 = fmaf(xv.y, wreg[4 * k4 + 1], a1);
            a2 = fmaf(xv.z, wreg[4 * k4 + 2], a2);
            a3 = fmaf(xv.w, wreg[4 * k4 + 3], a3);
        }
        spT[kh][row][col] = (a0 + a1) + (a2 + a3);
    }
    __syncthreads();
    if (kh == 0) {
        float bb = b[col];
        float as = asrc[col];
        __half* hph = (__half*)g_hph8;
        for (int row = slot; row < nrows; row += 2) {
            int n = n0 + row;
            float acc = spT[0][row][col] + spT[1][row][col] + bb;
            hph[n * HD + col] = __float2half_rn(acc);
            float vs = fmaxf(acc, 0.f) * as;
#pragma unroll
            for (int o = 16; o > 0; o >>= 1)
                vs += __shfl_down_sync(0xffffffffu, vs, o);
            if (lane == 0) ((float*)&g_es2[n])[head] = vs;
        }
    }
}

// ---------------- fused edge pass (fp16 gathers, no e_dst) ----------------
__global__ void k_edge_agg(const int* __restrict__ src, const int* __restrict__ dst,
                           const int* __restrict__ hn,  const int* __restrict__ he) {
    int gt = blockIdx.x * 256 + threadIdx.x;
    int e = gt >> 4;
    int q = gt & 15;
    int lane = threadIdx.x & 31;
    int s = src[e], t = dst[e], mn = hn[e], r = he[e];
    float ex0 = 0.f, ex1 = 0.f;
    if (q == 0) {
        float2 es = __ldg(&g_es2[s]);
        float2 sm = __ldg(&g_sm2[mn]);
        float2 sr = __ldg(&g_sr2[r]);
        ex0 = __expf(es.x + sm.x + sr.x);
        ex1 = __expf(es.y + sm.y + sr.y);
        red_add_v2(&g_denom2[t], ex0, ex1);
    }
    int base = lane & ~15;
    ex0 = __shfl_sync(0xffffffffu, ex0, base);
    ex1 = __shfl_sync(0xffffffffu, ex1, base);
    float ex = (q & 8) ? ex1 : ex0;
    u64 va = __ldg(&g_hph8[s * 16 + q]);
    u64 vb = __ldg(&g_vmidh8[mn * 16 + q]);
    u64 vc = __ldg(&g_vrelh8[r * 16 + q]);
    __half2 a01 = ((__half2*)&va)[0], a23 = ((__half2*)&va)[1];
    __half2 b01 = ((__half2*)&vb)[0], b23 = ((__half2*)&vb)[1];
    __half2 c01 = ((__half2*)&vc)[0], c23 = ((__half2*)&vc)[1];
    __half2 s01 = __hadd2(__hadd2(a01, b01), c01);
    __half2 s23 = __hadd2(__hadd2(a23, b23), c23);
    float2 f01 = __half22float2(s01);
    float2 f23 = __half22float2(s23);
    float4 v;
    v.x = ex * f01.x;
    v.y = ex * f01.y;
    v.z = ex * f23.x;
    v.w = ex * f23.y;
    red_add_v4(((float*)g_rst4) + (size_t)t * HD + q * 4, v);
}

// ---------------- final: float4/thread, 16 nodes/block ----------------
__global__ void __launch_bounds__(256) k_final(const float* __restrict__ b_edge,
                                               float* __restrict__ out) {
    int tid = threadIdx.x;
    int nl = tid >> 4, q = tid & 15;
    int n = blockIdx.x * 16 + nl;
    int hd = q >> 3;
    float den = ((const float*)&g_denom2[n])[hd];
    float inv = (den > 0.f) ? 1.f / den : 0.f;
    float vbm = (den > 0.f) ? 1.f : 0.f;
    float4 rv = g_rst4[n * 16 + q];
    float4 vbq = ((const float4*)g_vb)[q];
    float4 be = ((const float4*)b_edge)[q & 7];
    u64 va = g_hph8[n * 16 + q];
    __half2 a01 = ((__half2*)&va)[0], a23 = ((__half2*)&va)[1];
    float2 h01 = __half22float2(a01);
    float2 h23 = __half22float2(a23);
    float4 val;
    val.x = fmaxf(fmaf(rv.x, inv, vbq.x * vbm) + be.x + h01.x, 0.f);
    val.y = fmaxf(fmaf(rv.y, inv, vbq.y * vbm) + be.y + h01.y, 0.f);
    val.z = fmaxf(fmaf(rv.z, inv, vbq.z * vbm) + be.z + h23.x, 0.f);
    val.w = fmaxf(fmaf(rv.w, inv, vbq.w * vbm) + be.w + h23.y, 0.f);
    float ss = val.x * val.x + val.y * val.y + val.z * val.z + val.w * val.w;
#pragma unroll
    for (int o = 8; o > 0; o >>= 1) ss += __shfl_xor_sync(0xffffffffu, ss, o, 16);
    float norm = fmaxf(sqrtf(ss), 1e-12f);
    float rn = 1.f / norm;
    float4 o4;
    o4.x = val.x * rn;
    o4.y = val.y * rn;
    o4.z = val.z * rn;
    o4.w = val.w * rn;
    ((float4*)out)[n * 16 + q] = o4;
}

extern "C" void kernel_launch(void* const* d_in, const int* in_sizes, int n_in,
                              void* d_out, int out_size) {
    const float* h         = (const float*)d_in[0];
    const float* W_t       = (const float*)d_in[1];
    const float* b_t       = (const float*)d_in[2];
    const float* nfeat_mid = (const float*)d_in[3];
    const float* W_mid     = (const float*)d_in[4];
    const float* b_mid     = (const float*)d_in[5];
    const float* efeat_rel = (const float*)d_in[6];
    const float* W_rel     = (const float*)d_in[7];
    const float* b_rel     = (const float*)d_in[8];
    const float* attn_src  = (const float*)d_in[9];
    const float* attn_edge = (const float*)d_in[11];
    const float* W_edge    = (const float*)d_in[12];
    const float* b_edge    = (const float*)d_in[13];
    const int*   src_idx   = (const int*)d_in[14];
    const int*   dst_idx   = (const int*)d_in[15];
    const int*   hn        = (const int*)d_in[16];
    const int*   he        = (const int*)d_in[17];
    float* out = (float*)d_out;

    static cudaStream_t sB = 0, sC = 0, sD = 0;
    static cudaEvent_t evFork = 0, evB = 0, evC = 0, evD = 0;
    if (sB == 0) {
        cudaStreamCreateWithFlags(&sB, cudaStreamNonBlocking);
        cudaStreamCreateWithFlags(&sC, cudaStreamNonBlocking);
        cudaStreamCreateWithFlags(&sD, cudaStreamNonBlocking);
        cudaEventCreateWithFlags(&evFork, cudaEventDisableTiming);
        cudaEventCreateWithFlags(&evB, cudaEventDisableTiming);
        cudaEventCreateWithFlags(&evC, cudaEventDisableTiming);
        cudaEventCreateWithFlags(&evD, cudaEventDisableTiming);
    }

    // main stream: prep (fp16 B matrices, vb) then fork
    k_prep<<<1, 256>>>(W_mid, W_rel, b_mid, b_rel, W_edge);
    cudaEventRecord(evFork, 0);

    // branch B: target projection (fp32)
    cudaStreamWaitEvent(sB, evFork, 0);
    k_proj_target<<<(NN + 31) / 32, 256, 0, sB>>>(h, W_t, b_t, attn_src);
    cudaEventRecord(evB, sB);

    // branch C: mid projection via tensor cores (wmma)
    cudaStreamWaitEvent(sC, evFork, 0);
    k_mma_mid<<<NN / 16, 128, 0, sC>>>(nfeat_mid, b_mid, attn_edge);
    cudaEventRecord(evC, sC);

    // branch D: rel projection via tensor cores (wmma)
    cudaStreamWaitEvent(sD, evFork, 0);
    k_mma_rel<<<ERELN / 16, 128, 0, sD>>>(efeat_rel, b_rel, attn_edge);
    cudaEventRecord(evD, sD);

    // main stream: zero accumulators (overlaps projections)
    k_init_zero<<<(NN * 16 + 255) / 256, 256>>>();

    // join
    cudaStreamWaitEvent(0, evB, 0);
    cudaStreamWaitEvent(0, evC, 0);
    cudaStreamWaitEvent(0, evD, 0);
    k_edge_agg<<<(EE * 16) / 256, 256>>>(src_idx, dst_idx, hn, he);
    k_final<<<NN / 16, 256>>>(b_edge, out);
}

// round 17
// speedup vs baseline: 1.8639x; 1.1195x over previous
#include <cuda_runtime.h>
#include <cuda_fp16.h>
#include <mma.h>

using namespace nvcuda;

typedef unsigned long long u64;

#define NN     50000
#define EE     800000
#define HH     2
#define DD     32
#define HD     64
#define INDIM  64
#define ERELN  200000
#define DRELN  32

// ---------------- scratch ----------------
__device__ u64      g_hph8[NN * 16];       // half hp (edge gather + residual)
__device__ u64      g_vmidh8[NN * 16];
__device__ u64      g_vrelh8[ERELN * 16];
__device__ float2   g_es2[NN];
__device__ float2   g_sm2[NN];
__device__ float2   g_sr2[ERELN];
__device__ float2   g_denom2[NN];
__device__ float4   g_rst4[NN * 16];
__device__ __half   g_Bmid_h[INDIM * 128];   // [k][n]: W_mid | W_mid@We_top
__device__ __half   g_Brel_h[DRELN * 128];   // [k][n]: W_rel | W_rel@We_bot
__device__ float    g_vb[HD];

// ---------------- helpers ----------------
__device__ __forceinline__ void red_add_v4(float* p, float4 v) {
    asm volatile("red.global.add.v4.f32 [%0], {%1,%2,%3,%4};"
                 :: "l"(p), "f"(v.x), "f"(v.y), "f"(v.z), "f"(v.w) : "memory");
}
__device__ __forceinline__ void red_add_v2(float2* p, float a, float b) {
    asm volatile("red.global.add.v2.f32 [%0], {%1,%2};"
                 :: "l"(p), "f"(a), "f"(b) : "memory");
}
__device__ __forceinline__ u64 pack_h4(float a, float b, float c, float d) {
    __half2 lo = __floats2half2_rn(a, b);
    __half2 hi = __floats2half2_rn(c, d);
    unsigned ulo = *(unsigned*)&lo;
    unsigned uhi = *(unsigned*)&hi;
    return ((u64)uhi << 32) | (u64)ulo;
}

// ---------------- prep: fp16 fused B matrices + vb (1 block) ----------------
__global__ void k_prep(const float* __restrict__ W_mid, const float* __restrict__ W_rel,
                       const float* __restrict__ b_mid, const float* __restrict__ b_rel,
                       const float* __restrict__ We) {
    int tid = threadIdx.x;
    __shared__ float sWe[64 * 32];
    for (int i = tid; i < 2048; i += 256) sWe[i] = We[i];
    __syncthreads();
    for (int idx = tid; idx < INDIM * 128; idx += 256) {
        int k = idx >> 7;
        int n = idx & 127;
        float v;
        if (n < 64) {
            v = W_mid[k * 64 + n];
        } else {
            int c = n - 64;
            int hh = c >> 5;
            int d = c & 31;
            float acc = 0.f;
            for (int dd = 0; dd < 32; dd++)
                acc = fmaf(W_mid[k * 64 + hh * 32 + dd], sWe[dd * 32 + d], acc);
            v = acc;
        }
        g_Bmid_h[idx] = __float2half(v);
    }
    for (int idx = tid; idx < DRELN * 128; idx += 256) {
        int k = idx >> 7;
        int n = idx & 127;
        float v;
        if (n < 64) {
            v = W_rel[k * 64 + n];
        } else {
            int c = n - 64;
            int hh = c >> 5;
            int d = c & 31;
            float acc = 0.f;
            for (int dd = 0; dd < 32; dd++)
                acc = fmaf(W_rel[k * 64 + hh * 32 + dd], sWe[(32 + dd) * 32 + d], acc);
            v = acc;
        }
        g_Brel_h[idx] = __float2half(v);
    }
    if (tid < HD) {
        int hh = tid >> 5;
        int d = tid & 31;
        float acc = 0.f;
        for (int dd = 0; dd < 32; dd++) {
            acc = fmaf(b_mid[hh * 32 + dd], sWe[dd * 32 + d], acc);
            acc = fmaf(b_rel[hh * 32 + dd], sWe[(32 + dd) * 32 + d], acc);
        }
        g_vb[tid] = acc;
    }
}

// ---------------- zero-init accumulators ----------------
__global__ void k_init_zero() {
    int i = blockIdx.x * 256 + threadIdx.x;
    if (i < NN * 16) g_rst4[i] = make_float4(0.f, 0.f, 0.f, 0.f);
    if (i < NN)      g_denom2[i] = make_float2(0.f, 0.f);
}

// ---------------- mid projection via wmma: 4 row-tiles/block, B staged once ----------------
// 128 thr = 4 warps; warp w owns rows [(blk*4+w)*16, +16), computes all 128 cols in 2 halves.
__global__ void __launch_bounds__(128) k_mma_mid(const float* __restrict__ x,
                                                 const float* __restrict__ bias,
                                                 const float* __restrict__ aedge) {
    __shared__ __half sB[64][136];
    __shared__ __half sA[4][16][72];
    __shared__ float  sC[4][16][72];
    __shared__ float  sBias[64];
    __shared__ float  sAttn[64];
    int tid = threadIdx.x;
    int w = tid >> 5;
    int lane = tid & 31;

    for (int i = tid; i < 1024; i += 128) {
        int r = i >> 4;
        int c = i & 15;
        ((uint4*)&sB[r][0])[c] = ((const uint4*)g_Bmid_h)[i];
    }
    if (tid < 64) {
        sBias[tid] = bias[tid];
        sAttn[tid] = aedge[(tid >> 5) * 64 + (tid & 31)];
    }
    int row0 = (blockIdx.x * 4 + w) * 16;
    bool active = row0 < NN;
    if (active) {
        const float4* xg = (const float4*)(x + (size_t)row0 * 64);
        for (int j = lane; j < 256; j += 32) {
            int r = j >> 4;
            int c4 = j & 15;
            float4 v = xg[j];
            __half2* d2 = (__half2*)&sA[w][r][c4 * 4];
            d2[0] = __floats2half2_rn(v.x, v.y);
            d2[1] = __floats2half2_rn(v.z, v.w);
        }
    }
    __syncthreads();
    if (!active) return;

    wmma::fragment<wmma::matrix_a, 16, 16, 16, __half, wmma::row_major> fa[4];
    for (int ks = 0; ks < 4; ks++)
        wmma::load_matrix_sync(fa[ks], &sA[w][0][ks * 16], 72);
    wmma::fragment<wmma::matrix_b, 16, 16, 16, __half, wmma::row_major> fb;
    wmma::fragment<wmma::accumulator, 16, 16, 16, float> fc[4];

    // half 0: cols 0..63 -> logits
    for (int nt = 0; nt < 4; nt++) {
        wmma::fill_fragment(fc[nt], 0.f);
        for (int ks = 0; ks < 4; ks++) {
            wmma::load_matrix_sync(fb, &sB[ks * 16][nt * 16], 136);
            wmma::mma_sync(fc[nt], fa[ks], fb, fc[nt]);
        }
        wmma::store_matrix_sync(&sC[w][0][nt * 16], fc[nt], 72, wmma::mem_row_major);
    }
    __syncwarp();
    {
        int r = lane >> 1;
        int off = (lane & 1) * 32;
        float p = 0.f;
#pragma unroll
        for (int j = 0; j < 32; j++) {
            int c = off + j;
            p += fmaxf(sC[w][r][c] + sBias[c], 0.f) * sAttn[c];
        }
        float other = __shfl_down_sync(0xffffffffu, p, 1);
        if ((lane & 1) == 0) g_sm2[row0 + r] = make_float2(p, other);
    }
    __syncwarp();
    // half 1: cols 64..127 -> fp16 table
    for (int nt = 0; nt < 4; nt++) {
        wmma::fill_fragment(fc[nt], 0.f);
        for (int ks = 0; ks < 4; ks++) {
            wmma::load_matrix_sync(fb, &sB[ks * 16][64 + nt * 16], 136);
            wmma::mma_sync(fc[nt], fa[ks], fb, fc[nt]);
        }
        wmma::store_matrix_sync(&sC[w][0][nt * 16], fc[nt], 72, wmma::mem_row_major);
    }
    __syncwarp();
    for (int i = lane; i < 256; i += 32) {
        int r = i >> 4;
        int c = i & 15;
        const float* cp = &sC[w][r][c * 4];
        g_vmidh8[(size_t)(row0 + r) * 16 + c] = pack_h4(cp[0], cp[1], cp[2], cp[3]);
    }
}

// ---------------- rel projection via wmma: 4 row-tiles/block ----------------
__global__ void __launch_bounds__(128) k_mma_rel(const float* __restrict__ x,
                                                 const float* __restrict__ bias,
                                                 const float* __restrict__ aedge) {
    __shared__ __half sB[32][136];
    __shared__ __half sA[4][16][40];
    __shared__ float  sC[4][16][72];
    __shared__ float  sBias[64];
    __shared__ float  sAttn[64];
    int tid = threadIdx.x;
    int w = tid >> 5;
    int lane = tid & 31;

    for (int i = tid; i < 512; i += 128) {
        int r = i >> 4;
        int c = i & 15;
        ((uint4*)&sB[r][0])[c] = ((const uint4*)g_Brel_h)[i];
    }
    if (tid < 64) {
        sBias[tid] = bias[tid];
        sAttn[tid] = aedge[(tid >> 5) * 64 + 32 + (tid & 31)];
    }
    int row0 = (blockIdx.x * 4 + w) * 16;
    {
        const float4* xg = (const float4*)(x + (size_t)row0 * 32);
        for (int j = lane; j < 128; j += 32) {
            int r = j >> 3;
            int c4 = j & 7;
            float4 v = xg[j];
            __half2* d2 = (__half2*)&sA[w][r][c4 * 4];
            d2[0] = __floats2half2_rn(v.x, v.y);
            d2[1] = __floats2half2_rn(v.z, v.w);
        }
    }
    __syncthreads();

    wmma::fragment<wmma::matrix_a, 16, 16, 16, __half, wmma::row_major> fa[2];
    for (int ks = 0; ks < 2; ks++)
        wmma::load_matrix_sync(fa[ks], &sA[w][0][ks * 16], 40);
    wmma::fragment<wmma::matrix_b, 16, 16, 16, __half, wmma::row_major> fb;
    wmma::fragment<wmma::accumulator, 16, 16, 16, float> fc[4];

    for (int nt = 0; nt < 4; nt++) {
        wmma::fill_fragment(fc[nt], 0.f);
        for (int ks = 0; ks < 2; ks++) {
            wmma::load_matrix_sync(fb, &sB[ks * 16][nt * 16], 136);
            wmma::mma_sync(fc[nt], fa[ks], fb, fc[nt]);
        }
        wmma::store_matrix_sync(&sC[w][0][nt * 16], fc[nt], 72, wmma::mem_row_major);
    }
    __syncwarp();
    {
        int r = lane >> 1;
        int off = (lane & 1) * 32;
        float p = 0.f;
#pragma unroll
        for (int j = 0; j < 32; j++) {
            int c = off + j;
            p += fmaxf(sC[w][r][c] + sBias[c], 0.f) * sAttn[c];
        }
        float other = __shfl_down_sync(0xffffffffu, p, 1);
        if ((lane & 1) == 0) g_sr2[row0 + r] = make_float2(p, other);
    }
    __syncwarp();
    for (int nt = 0; nt < 4; nt++) {
        wmma::fill_fragment(fc[nt], 0.f);
        for (int ks = 0; ks < 2; ks++) {
            wmma::load_matrix_sync(fb, &sB[ks * 16][64 + nt * 16], 136);
            wmma::mma_sync(fc[nt], fa[ks], fb, fc[nt]);
        }
        wmma::store_matrix_sync(&sC[w][0][nt * 16], fc[nt], 72, wmma::mem_row_major);
    }
    __syncwarp();
    for (int i = lane; i < 256; i += 32) {
        int r = i >> 4;
        int c = i & 15;
        const float* cp = &sC[w][r][c * 4];
        g_vrelh8[(size_t)(row0 + r) * 16 + c] = pack_h4(cp[0], cp[1], cp[2], cp[3]);
    }
}

// ---------------- target projection via wmma: hp(half) + e_src ----------------
__global__ void __launch_bounds__(128) k_mma_tgt(const float* __restrict__ x,
                                                 const float* __restrict__ W,
                                                 const float* __restrict__ bias,
                                                 const float* __restrict__ asrc) {
    __shared__ __half sB[64][72];
    __shared__ __half sA[4][16][72];
    __shared__ float  sC[4][16][72];
    __shared__ float  sBias[64];
    __shared__ float  sAsrc[64];
    int tid = threadIdx.x;
    int w = tid >> 5;
    int lane = tid & 31;

    // stage B: W_t [64k][64n] fp32 -> fp16 (1024 float4)
    for (int i = tid; i < 1024; i += 128) {
        int r = i >> 4;
        int c4 = i & 15;
        float4 v = ((const float4*)W)[i];
        __half2* d2 = (__half2*)&sB[r][c4 * 4];
        d2[0] = __floats2half2_rn(v.x, v.y);
        d2[1] = __floats2half2_rn(v.z, v.w);
    }
    if (tid < 64) {
        sBias[tid] = bias[tid];
        sAsrc[tid] = asrc[tid];
    }
    int row0 = (blockIdx.x * 4 + w) * 16;
    bool active = row0 < NN;
    if (active) {
        const float4* xg = (const float4*)(x + (size_t)row0 * 64);
        for (int j = lane; j < 256; j += 32) {
            int r = j >> 4;
            int c4 = j & 15;
            float4 v = xg[j];
            __half2* d2 = (__half2*)&sA[w][r][c4 * 4];
            d2[0] = __floats2half2_rn(v.x, v.y);
            d2[1] = __floats2half2_rn(v.z, v.w);
        }
    }
    __syncthreads();
    if (!active) return;

    wmma::fragment<wmma::matrix_a, 16, 16, 16, __half, wmma::row_major> fa[4];
    for (int ks = 0; ks < 4; ks++)
        wmma::load_matrix_sync(fa[ks], &sA[w][0][ks * 16], 72);
    wmma::fragment<wmma::matrix_b, 16, 16, 16, __half, wmma::row_major> fb;
    wmma::fragment<wmma::accumulator, 16, 16, 16, float> fc[4];

    for (int nt = 0; nt < 4; nt++) {
        wmma::fill_fragment(fc[nt], 0.f);
        for (int ks = 0; ks < 4; ks++) {
            wmma::load_matrix_sync(fb, &sB[ks * 16][nt * 16], 72);
            wmma::mma_sync(fc[nt], fa[ks], fb, fc[nt]);
        }
        wmma::store_matrix_sync(&sC[w][0][nt * 16], fc[nt], 72, wmma::mem_row_major);
    }
    __syncwarp();
    {
        int r = lane >> 1;
        int off = (lane & 1) * 32;
        float p = 0.f;
#pragma unroll
        for (int k = 0; k < 8; k++) {
            int c0 = off + k * 4;
            const float* cp = &sC[w][r][c0];
            float v0 = cp[0] + sBias[c0 + 0];
            float v1 = cp[1] + sBias[c0 + 1];
            float v2 = cp[2] + sBias[c0 + 2];
            float v3 = cp[3] + sBias[c0 + 3];
            p += fmaxf(v0, 0.f) * sAsrc[c0 + 0];
            p += fmaxf(v1, 0.f) * sAsrc[c0 + 1];
            p += fmaxf(v2, 0.f) * sAsrc[c0 + 2];
            p += fmaxf(v3, 0.f) * sAsrc[c0 + 3];
            g_hph8[(size_t)(row0 + r) * 16 + (c0 >> 2)] = pack_h4(v0, v1, v2, v3);
        }
        float other = __shfl_down_sync(0xffffffffu, p, 1);
        if ((lane & 1) == 0) g_es2[row0 + r] = make_float2(p, other);
    }
}

// ---------------- fused edge pass (fp16 gathers, no e_dst) ----------------
__global__ void k_edge_agg(const int* __restrict__ src, const int* __restrict__ dst,
                           const int* __restrict__ hn,  const int* __restrict__ he) {
    int gt = blockIdx.x * 256 + threadIdx.x;
    int e = gt >> 4;
    int q = gt & 15;
    int lane = threadIdx.x & 31;
    int s = src[e], t = dst[e], mn = hn[e], r = he[e];
    float ex0 = 0.f, ex1 = 0.f;
    if (q == 0) {
        float2 es = __ldg(&g_es2[s]);
        float2 sm = __ldg(&g_sm2[mn]);
        float2 sr = __ldg(&g_sr2[r]);
        ex0 = __expf(es.x + sm.x + sr.x);
        ex1 = __expf(es.y + sm.y + sr.y);
        red_add_v2(&g_denom2[t], ex0, ex1);
    }
    int base = lane & ~15;
    ex0 = __shfl_sync(0xffffffffu, ex0, base);
    ex1 = __shfl_sync(0xffffffffu, ex1, base);
    float ex = (q & 8) ? ex1 : ex0;
    u64 va = __ldg(&g_hph8[s * 16 + q]);
    u64 vb = __ldg(&g_vmidh8[mn * 16 + q]);
    u64 vc = __ldg(&g_vrelh8[r * 16 + q]);
    __half2 a01 = ((__half2*)&va)[0], a23 = ((__half2*)&va)[1];
    __half2 b01 = ((__half2*)&vb)[0], b23 = ((__half2*)&vb)[1];
    __half2 c01 = ((__half2*)&vc)[0], c23 = ((__half2*)&vc)[1];
    __half2 s01 = __hadd2(__hadd2(a01, b01), c01);
    __half2 s23 = __hadd2(__hadd2(a23, b23), c23);
    float2 f01 = __half22float2(s01);
    float2 f23 = __half22float2(s23);
    float4 v;
    v.x = ex * f01.x;
    v.y = ex * f01.y;
    v.z = ex * f23.x;
    v.w = ex * f23.y;
    red_add_v4(((float*)g_rst4) + (size_t)t * HD + q * 4, v);
}

// ---------------- final: float4/thread, 16 nodes/block ----------------
__global__ void __launch_bounds__(256) k_final(const float* __restrict__ b_edge,
                                               float* __restrict__ out) {
    int tid = threadIdx.x;
    int nl = tid >> 4, q = tid & 15;
    int n = blockIdx.x * 16 + nl;
    int hd = q >> 3;
    float den = ((const float*)&g_denom2[n])[hd];
    float inv = (den > 0.f) ? 1.f / den : 0.f;
    float vbm = (den > 0.f) ? 1.f : 0.f;
    float4 rv = g_rst4[n * 16 + q];
    float4 vbq = ((const float4*)g_vb)[q];
    float4 be = ((const float4*)b_edge)[q & 7];
    u64 va = g_hph8[n * 16 + q];
    __half2 a01 = ((__half2*)&va)[0], a23 = ((__half2*)&va)[1];
    float2 h01 = __half22float2(a01);
    float2 h23 = __half22float2(a23);
    float4 val;
    val.x = fmaxf(fmaf(rv.x, inv, vbq.x * vbm) + be.x + h01.x, 0.f);
    val.y = fmaxf(fmaf(rv.y, inv, vbq.y * vbm) + be.y + h01.y, 0.f);
    val.z = fmaxf(fmaf(rv.z, inv, vbq.z * vbm) + be.z + h23.x, 0.f);
    val.w = fmaxf(fmaf(rv.w, inv, vbq.w * vbm) + be.w + h23.y, 0.f);
    float ss = val.x * val.x + val.y * val.y + val.z * val.z + val.w * val.w;
#pragma unroll
    for (int o = 8; o > 0; o >>= 1) ss += __shfl_xor_sync(0xffffffffu, ss, o, 16);
    float norm = fmaxf(sqrtf(ss), 1e-12f);
    float rn = 1.f / norm;
    float4 o4;
    o4.x = val.x * rn;
    o4.y = val.y * rn;
    o4.z = val.z * rn;
    o4.w = val.w * rn;
    ((float4*)out)[n * 16 + q] = o4;
}

extern "C" void kernel_launch(void* const* d_in, const int* in_sizes, int n_in,
                              void* d_out, int out_size) {
    const float* h         = (const float*)d_in[0];
    const float* W_t       = (const float*)d_in[1];
    const float* b_t       = (const float*)d_in[2];
    const float* nfeat_mid = (const float*)d_in[3];
    const float* W_mid     = (const float*)d_in[4];
    const float* b_mid     = (const float*)d_in[5];
    const float* efeat_rel = (const float*)d_in[6];
    const float* W_rel     = (const float*)d_in[7];
    const float* b_rel     = (const float*)d_in[8];
    const float* attn_src  = (const float*)d_in[9];
    const float* attn_edge = (const float*)d_in[11];
    const float* W_edge    = (const float*)d_in[12];
    const float* b_edge    = (const float*)d_in[13];
    const int*   src_idx   = (const int*)d_in[14];
    const int*   dst_idx   = (const int*)d_in[15];
    const int*   hn        = (const int*)d_in[16];
    const int*   he        = (const int*)d_in[17];
    float* out = (float*)d_out;

    static cudaStream_t sB = 0, sC = 0, sD = 0;
    static cudaEvent_t evFork = 0, evB = 0, evC = 0, evD = 0;
    if (sB == 0) {
        cudaStreamCreateWithFlags(&sB, cudaStreamNonBlocking);
        cudaStreamCreateWithFlags(&sC, cudaStreamNonBlocking);
        cudaStreamCreateWithFlags(&sD, cudaStreamNonBlocking);
        cudaEventCreateWithFlags(&evFork, cudaEventDisableTiming);
        cudaEventCreateWithFlags(&evB, cudaEventDisableTiming);
        cudaEventCreateWithFlags(&evC, cudaEventDisableTiming);
        cudaEventCreateWithFlags(&evD, cudaEventDisableTiming);
    }

    // main stream: prep (fp16 B matrices, vb) then fork
    k_prep<<<1, 256>>>(W_mid, W_rel, b_mid, b_rel, W_edge);
    cudaEventRecord(evFork, 0);

    // branch B: target projection via tensor cores
    cudaStreamWaitEvent(sB, evFork, 0);
    k_mma_tgt<<<(NN / 16 + 3) / 4, 128, 0, sB>>>(h, W_t, b_t, attn_src);
    cudaEventRecord(evB, sB);

    // branch C: mid projection via tensor cores
    cudaStreamWaitEvent(sC, evFork, 0);
    k_mma_mid<<<(NN / 16 + 3) / 4, 128, 0, sC>>>(nfeat_mid, b_mid, attn_edge);
    cudaEventRecord(evC, sC);

    // branch D: rel projection via tensor cores
    cudaStreamWaitEvent(sD, evFork, 0);
    k_mma_rel<<<ERELN / 64, 128, 0, sD>>>(efeat_rel, b_rel, attn_edge);
    cudaEventRecord(evD, sD);

    // main stream: zero accumulators (overlaps projections)
    k_init_zero<<<(NN * 16 + 255) / 256, 256>>>();

    // join
    cudaStreamWaitEvent(0, evB, 0);
    cudaStreamWaitEvent(0, evC, 0);
    cudaStreamWaitEvent(0, evD, 0);
    k_edge_agg<<<(EE * 16) / 256, 256>>>(src_idx, dst_idx, hn, he);
    k_final<<<NN / 16, 256>>>(b_edge, out);
}